// round 8
// baseline (speedup 1.0000x reference)
#include <cuda_runtime.h>
#include <cuda_fp16.h>
#include <math.h>
#include <stdint.h>

#define BATCH   4
#define SEQ     4096
#define DMODEL  1024
#define HEADS   16
#define DKC     64
#define HALF    512
#define NSEG    4
#define MTOT    (BATCH * SEQ)    /* 16384 */

// ---------------- scratch (device globals; no allocations) ----------------
__device__ float g_cos[SEQ * HALF];
__device__ float g_sin[SEQ * HALF];
__device__ float g_qs[BATCH * DKC * DMODEL];
__device__ float g_qs_part[NSEG * BATCH * DKC * DMODEL];
__device__ float g_kp_part[NSEG * BATCH * DKC * DMODEL];
__device__ float g_T_part [NSEG * BATCH * DKC * DMODEL];
__device__ float g_kp[BATCH * DKC * DMODEL];            // kp[b][e][d]
__device__ float g_T [BATCH * DKC * DMODEL];            // T[b][e][c]
__device__ float g_vp[BATCH * DMODEL * DKC];            // vp[b][f][e]
__device__ float g_ysmall[BATCH * DKC * DMODEL];
__device__ float g_z[BATCH * DKC * DMODEL];
__device__ float g_zbar[BATCH * DMODEL];

// int8 slices (activations + weights for wk/wg GEMMs)
__device__ int8_t g_q8a[MTOT * DMODEL], g_q8b[MTOT * DMODEL];
__device__ int8_t g_k8a[MTOT * DMODEL], g_k8b[MTOT * DMODEL];
__device__ int8_t g_wk8a[DMODEL * DMODEL], g_wk8b[DMODEL * DMODEL];
__device__ int8_t g_wg8a[DMODEL * DMODEL], g_wg8b[DMODEL * DMODEL];
__device__ int    g_amax[4];   // 0:q 1:k 2:wk 3:wg (abs-max as float bits)

// fp16 split operands (wo GEMM path + seq GEMMs)
__device__ __half g_ahi[MTOT * DMODEL], g_alo[MTOT * DMODEL];   // silu(gate)
__device__ __half g_wohi[DMODEL * DMODEL], g_wolo[DMODEL * DMODEL];
__device__ __half g_wxhi[DKC * SEQ],       g_wxlo[DKC * SEQ];
// transposed seq-major operands [b*DMODEL + d][SEQ]
__device__ __half g_kxThi[BATCH * DMODEL * SEQ], g_kxTlo[BATCH * DMODEL * SEQ];
__device__ __half g_vThi [BATCH * DMODEL * SEQ], g_vTlo [BATCH * DMODEL * SEQ];

// ================= PTX helpers =================
__device__ __forceinline__ uint32_t smem_u32(const void* p) {
    uint32_t a;
    asm("{ .reg .u64 t; cvta.to.shared.u64 t, %1; cvt.u32.u64 %0, t; }" : "=r"(a) : "l"(p));
    return a;
}
__device__ __forceinline__ void cp16(uint32_t dst, const void* src) {
    asm volatile("cp.async.cg.shared.global [%0], [%1], 16;" :: "r"(dst), "l"(src) : "memory");
}
#define CP_COMMIT() asm volatile("cp.async.commit_group;" ::: "memory")
#define CP_WAIT(N)  asm volatile("cp.async.wait_group %0;" :: "n"(N) : "memory")

__device__ __forceinline__ void ldsm4(uint32_t* r, uint32_t addr) {
    asm volatile("ldmatrix.sync.aligned.m8n8.x4.shared.b16 {%0,%1,%2,%3}, [%4];"
                 : "=r"(r[0]), "=r"(r[1]), "=r"(r[2]), "=r"(r[3]) : "r"(addr));
}
__device__ __forceinline__ void mma16816(float* d, const uint32_t* a, const uint32_t* b) {
    asm volatile("mma.sync.aligned.m16n8k16.row.col.f32.f16.f16.f32 "
                 "{%0,%1,%2,%3}, {%4,%5,%6,%7}, {%8,%9}, {%0,%1,%2,%3};"
                 : "+f"(d[0]), "+f"(d[1]), "+f"(d[2]), "+f"(d[3])
                 : "r"(a[0]), "r"(a[1]), "r"(a[2]), "r"(a[3]), "r"(b[0]), "r"(b[1]));
}
__device__ __forceinline__ void imma16832(int* d, const uint32_t* a, const uint32_t* b) {
    asm volatile("mma.sync.aligned.m16n8k32.row.col.s32.s8.s8.s32 "
                 "{%0,%1,%2,%3}, {%4,%5,%6,%7}, {%8,%9}, {%0,%1,%2,%3};"
                 : "+r"(d[0]), "+r"(d[1]), "+r"(d[2]), "+r"(d[3])
                 : "r"(a[0]), "r"(a[1]), "r"(a[2]), "r"(a[3]), "r"(b[0]), "r"(b[1]));
}

// SMEM: rows padded to 80B, 4 tiles x 128 rows per stage, 3 stages
#define ROWB      80
#define TILE_B    10240
#define STG_BYTES 40960
#define SMEM_MAIN (3 * STG_BYTES)   /* 122880 */
#define TP_PAD    136

// seq GEMM SMEM
#define SQ_STG    30720
#define SQ_ALO    5120
#define SQ_B      10240
#define SQ_BLO    10240
#define SMEM_SEQ  (3 * SQ_STG)

// ================= xpos tables =================
__global__ void build_tables() {
    int idx = blockIdx.x * blockDim.x + threadIdx.x;
    if (idx >= SEQ * HALF) return;
    int s = idx / HALF, i = idx % HALF;
    float sv    = (2.0f * i + 0.4f * DMODEL) / (1.4f * DMODEL);
    float scale = powf(sv, (float)s / 512.0f);
    float invf  = powf(10000.0f, -(float)i / (float)HALF);
    float ang   = (float)s * invf;
    g_cos[idx] = cosf(ang) * scale;
    g_sin[idx] = sinf(ang) * scale;
}

// ================= absmax / quantize =================
__global__ void reset_amax() {
    if (threadIdx.x < 4) g_amax[threadIdx.x] = 0;
}
__global__ void absmax_kernel(const float* __restrict__ x, int n4, int slot) {
    __shared__ float red[256];
    float m = 0.f;
    for (int i = blockIdx.x * 256 + threadIdx.x; i < n4; i += gridDim.x * 256) {
        float4 v = ((const float4*)x)[i];
        m = fmaxf(m, fmaxf(fmaxf(fabsf(v.x), fabsf(v.y)), fmaxf(fabsf(v.z), fabsf(v.w))));
    }
    red[threadIdx.x] = m;
    __syncthreads();
    for (int s = 128; s > 0; s >>= 1) {
        if (threadIdx.x < s) red[threadIdx.x] = fmaxf(red[threadIdx.x], red[threadIdx.x + s]);
        __syncthreads();
    }
    if (threadIdx.x == 0) atomicMax(&g_amax[slot], __float_as_int(red[0]));
}
__global__ void quant8(const float* __restrict__ x, int slot,
                       int8_t* __restrict__ q1, int8_t* __restrict__ q2, int n4) {
    int i = blockIdx.x * blockDim.x + threadIdx.x;
    if (i >= n4) return;
    float s = 127.0f / __int_as_float(g_amax[slot]);
    float4 v = ((const float4*)x)[i];
    float a0 = v.x * s, a1 = v.y * s, a2 = v.z * s, a3 = v.w * s;
    int i0 = __float2int_rn(a0), i1 = __float2int_rn(a1);
    int i2 = __float2int_rn(a2), i3 = __float2int_rn(a3);
    int j0 = __float2int_rn((a0 - i0) * 128.f), j1 = __float2int_rn((a1 - i1) * 128.f);
    int j2 = __float2int_rn((a2 - i2) * 128.f), j3 = __float2int_rn((a3 - i3) * 128.f);
    ((char4*)q1)[i] = make_char4((char)i0, (char)i1, (char)i2, (char)i3);
    ((char4*)q2)[i] = make_char4((char)j0, (char)j1, (char)j2, (char)j3);
}

// ================= fp32 -> (hi, lo) fp16 split =================
__global__ void split_half(const float* __restrict__ x, __half* __restrict__ hi,
                           __half* __restrict__ lo, int n4) {
    int i = blockIdx.x * blockDim.x + threadIdx.x;
    if (i >= n4) return;
    float4 v = ((const float4*)x)[i];
    __half h0 = __float2half(v.x), h1 = __float2half(v.y);
    __half h2 = __float2half(v.z), h3 = __float2half(v.w);
    __half l0 = __float2half(v.x - __half2float(h0));
    __half l1 = __float2half(v.y - __half2float(h1));
    __half l2 = __float2half(v.z - __half2float(h2));
    __half l3 = __float2half(v.w - __half2float(h3));
    __half2* ph = (__half2*)(hi) + i * 2;
    __half2* pl = (__half2*)(lo) + i * 2;
    ph[0] = __half2(h0, h1); ph[1] = __half2(h2, h3);
    pl[0] = __half2(l0, l1); pl[1] = __half2(l2, l3);
}

// ================= v -> vT hi/lo (transpose + split) =================
__global__ __launch_bounds__(256)
void vt_split(const float* __restrict__ v, __half* __restrict__ th,
              __half* __restrict__ tl)
{
    __shared__ float ts[64][65];
    const int s0 = blockIdx.x * 64, c0 = blockIdx.y * 64, b = blockIdx.z;
    const int tid = threadIdx.x;
    const int r = tid >> 2, quad = tid & 3;
#pragma unroll
    for (int j = 0; j < 4; ++j) {
        int col = quad * 16 + j * 4;
        float4 x = *(const float4*)(v + ((size_t)b * SEQ + s0 + r) * DMODEL + c0 + col);
        ts[r][col] = x.x; ts[r][col + 1] = x.y; ts[r][col + 2] = x.z; ts[r][col + 3] = x.w;
    }
    __syncthreads();
    uint4 hv[2], lv[2];
    __half* hh = (__half*)hv;
    __half* ll = (__half*)lv;
#pragma unroll
    for (int j = 0; j < 16; ++j) {
        float x = ts[quad * 16 + j][r];
        hh[j] = __float2half(x);
        ll[j] = __float2half(x - __half2float(hh[j]));
    }
    size_t row = ((size_t)b * DMODEL + c0 + r) * SEQ + s0 + quad * 16;
    *(uint4*)(th + row) = hv[0]; *(uint4*)(th + row + 8) = hv[1];
    *(uint4*)(tl + row) = lv[0]; *(uint4*)(tl + row + 8) = lv[1];
}

// ================= int8 IMMA split GEMM: C[m,n] = sum_k A[m,k]*W[n,k] =================
// CTA 128x128, 16 warps, warp tile 32x32, K chunks of 64 int8 (2 ksteps of 32), 3-stage.
// 3 mma-sets: A1W1 -> accm ; A1W2 + A2W1 -> accl (both carry 1/128).
// EPI 1: xpos -> keyxT fp16 hi/lo transposed ; EPI 2: gate*z+silu -> fp16 hi/lo.
__device__ __forceinline__ void imma_load_stage(
    uint32_t sb, int slot, int kc, int m0, int n0, int tid,
    const int8_t* __restrict__ A1, const int8_t* __restrict__ A2,
    const int8_t* __restrict__ W1, const int8_t* __restrict__ W2)
{
    const uint32_t base = sb + (uint32_t)slot * STG_BYTES;
    const int koff = kc * 64;
#pragma unroll
    for (int it = 0; it < 4; ++it) {
        int i = it * 512 + tid;
        int tile = i >> 9, r = (i >> 2) & 127, u = i & 3;
        const int8_t* src;
        if      (tile == 0) src = A1 + (size_t)(m0 + r) * DMODEL + koff + u * 16;
        else if (tile == 1) src = A2 + (size_t)(m0 + r) * DMODEL + koff + u * 16;
        else if (tile == 2) src = W1 + (size_t)(n0 + r) * DMODEL + koff + u * 16;
        else                src = W2 + (size_t)(n0 + r) * DMODEL + koff + u * 16;
        cp16(base + (uint32_t)(tile * TILE_B + r * ROWB + u * 16), src);
    }
    CP_COMMIT();
}

template<int EPI>
__global__ __launch_bounds__(512)
void imma_gemm(const int8_t* __restrict__ A1, const int8_t* __restrict__ A2,
               const int8_t* __restrict__ W1, const int8_t* __restrict__ W2,
               int slotA, int slotW,
               __half* __restrict__ Chi, __half* __restrict__ Clo)
{
    extern __shared__ char smem[];
    const uint32_t sb = smem_u32(smem);
    const int tid = threadIdx.x, wid = tid >> 5, lane = tid & 31;
    const int warp_m = wid >> 2, warp_n = wid & 3;
    const int n0 = blockIdx.x * 128, m0 = blockIdx.y * 128;

    int accm[2][4][4], accl[2][4][4];
#pragma unroll
    for (int i = 0; i < 2; ++i)
#pragma unroll
        for (int j = 0; j < 4; ++j)
#pragma unroll
            for (int c = 0; c < 4; ++c) { accm[i][j][c] = 0; accl[i][j][c] = 0; }

    uint32_t aoff[2], boff[2];
#pragma unroll
    for (int a = 0; a < 2; ++a)
        aoff[a] = (uint32_t)((warp_m * 32 + a * 16 + (lane & 15)) * ROWB
                             + ((lane >> 4) & 1) * 16);
#pragma unroll
    for (int p = 0; p < 2; ++p)
        boff[p] = (uint32_t)((warp_n * 32 + p * 16 + (lane & 7) + ((lane >> 4) << 3)) * ROWB
                             + ((lane >> 3) & 1) * 16);

    imma_load_stage(sb, 0, 0, m0, n0, tid, A1, A2, W1, W2);
    imma_load_stage(sb, 1, 1, m0, n0, tid, A1, A2, W1, W2);

    for (int kc = 0; kc < 16; ++kc) {
        if (kc >= 14) { CP_WAIT(0); } else { CP_WAIT(1); }
        __syncthreads();
        if (kc + 2 < 16)
            imma_load_stage(sb, (kc + 2) % 3, kc + 2, m0, n0, tid, A1, A2, W1, W2);
        const uint32_t stgb = sb + (uint32_t)(kc % 3) * STG_BYTES;
#pragma unroll
        for (int ks = 0; ks < 2; ++ks) {
            const uint32_t kb = (uint32_t)(ks * 32);
            uint32_t a1[2][4], a2[2][4], w1[2][4], w2[2][4];
#pragma unroll
            for (int a = 0; a < 2; ++a) {
                ldsm4(a1[a], stgb + aoff[a] + kb);
                ldsm4(a2[a], stgb + TILE_B + aoff[a] + kb);
            }
#pragma unroll
            for (int p = 0; p < 2; ++p) {
                ldsm4(w1[p], stgb + 2 * TILE_B + boff[p] + kb);
                ldsm4(w2[p], stgb + 3 * TILE_B + boff[p] + kb);
            }
#pragma unroll
            for (int im = 0; im < 2; ++im)
#pragma unroll
                for (int in = 0; in < 4; ++in)
                    imma16832(accm[im][in], a1[im], &w1[in >> 1][(in & 1) * 2]);
#pragma unroll
            for (int im = 0; im < 2; ++im)
#pragma unroll
                for (int in = 0; in < 4; ++in)
                    imma16832(accl[im][in], a1[im], &w2[in >> 1][(in & 1) * 2]);
#pragma unroll
            for (int im = 0; im < 2; ++im)
#pragma unroll
                for (int in = 0; in < 4; ++in)
                    imma16832(accl[im][in], a2[im], &w1[in >> 1][(in & 1) * 2]);
        }
    }

    const float invAW = __int_as_float(g_amax[slotA]) * __int_as_float(g_amax[slotW])
                        * (1.0f / 16129.0f);

    // -------- epilogue --------
    if (EPI == 1) {
        __syncthreads();
        __half* sh = (__half*)smem;
        __half* sl = sh + 128 * TP_PAD;
#pragma unroll
        for (int im = 0; im < 2; ++im)
#pragma unroll
            for (int in = 0; in < 4; ++in) {
                const int dl = warp_n * 32 + in * 8 + (lane & 3) * 2;
                const int nc = n0 + dl;
#pragma unroll
                for (int half = 0; half < 2; ++half) {
                    const int ml = warp_m * 32 + im * 16 + (lane >> 2) + half * 8;
                    const int s = (m0 + ml) & (SEQ - 1);
                    float v0 = ((float)accm[im][in][half * 2 + 0]
                                + (float)accl[im][in][half * 2 + 0] * 0.0078125f) * invAW;
                    float v1 = ((float)accm[im][in][half * 2 + 1]
                                + (float)accl[im][in][half * 2 + 1] * 0.0078125f) * invAW;
                    int p = s * HALF + (nc >> 1);
                    float cs = g_cos[p], sn = g_sin[p];
                    float o0 = v0 * cs - v1 * sn;
                    float o1 = v1 * cs + v0 * sn;
                    __half h0 = __float2half(o0), h1 = __float2half(o1);
                    __half l0 = __float2half(o0 - __half2float(h0));
                    __half l1 = __float2half(o1 - __half2float(h1));
                    sh[dl * TP_PAD + ml] = h0; sh[(dl + 1) * TP_PAD + ml] = h1;
                    sl[dl * TP_PAD + ml] = l0; sl[(dl + 1) * TP_PAD + ml] = l1;
                }
            }
        __syncthreads();
        const int s0 = m0 & (SEQ - 1), bb = m0 >> 12;
#pragma unroll
        for (int it = 0; it < 4; ++it) {
            int slot = it * 512 + tid;
            int dr = slot >> 4;
            int sc = (slot & 15) * 8;
            size_t grow = ((size_t)(bb * DMODEL + n0 + dr)) * SEQ + s0 + sc;
            *(uint4*)(Chi + grow) = *(uint4*)(sh + dr * TP_PAD + sc);
            *(uint4*)(Clo + grow) = *(uint4*)(sl + dr * TP_PAD + sc);
        }
        return;
    }
    // EPI == 2
#pragma unroll
    for (int im = 0; im < 2; ++im) {
#pragma unroll
        for (int in = 0; in < 4; ++in) {
            const int nc = n0 + warp_n * 32 + in * 8 + (lane & 3) * 2;
#pragma unroll
            for (int half = 0; half < 2; ++half) {
                const int m = m0 + warp_m * 32 + im * 16 + (lane >> 2) + half * 8;
                const int s = m & (SEQ - 1);
                const int bb = m >> 12;
                float v0 = ((float)accm[im][in][half * 2 + 0]
                            + (float)accl[im][in][half * 2 + 0] * 0.0078125f) * invAW;
                float v1 = ((float)accm[im][in][half * 2 + 1]
                            + (float)accl[im][in][half * 2 + 1] * 0.0078125f) * invAW;
                const float* zr = (s < DKC) ? (g_z + (bb * DKC + s) * DMODEL)
                                            : (g_zbar + bb * DMODEL);
                float a0 = v0 * zr[nc];
                float a1 = v1 * zr[nc + 1];
                a0 = a0 / (1.f + expf(-a0));
                a1 = a1 / (1.f + expf(-a1));
                __half h0 = __float2half(a0), h1 = __float2half(a1);
                __half l0 = __float2half(a0 - __half2float(h0));
                __half l1 = __float2half(a1 - __half2float(h1));
                *(__half2*)(Chi + (size_t)m * DMODEL + nc) = __half2(h0, h1);
                *(__half2*)(Clo + (size_t)m * DMODEL + nc) = __half2(l0, l1);
            }
        }
    }
}

// ================= fp16 HMMA 2-pass GEMM (wo): C[m,n] = sum_k A*W =================
__device__ __forceinline__ void hmma_load_stage(
    uint32_t sb, int slot, int kc, int m0, int n0, int tid,
    const __half* __restrict__ Ahi, const __half* __restrict__ Alo,
    const __half* __restrict__ Whi)
{
    const uint32_t base = sb + (uint32_t)slot * STG_BYTES;
    const int koff = kc * 32;
#pragma unroll
    for (int it = 0; it < 3; ++it) {
        int i = it * 512 + tid;
        int tile = i >> 9, r = (i >> 2) & 127, u = i & 3;
        const __half* src;
        if      (tile == 0) src = Ahi + (size_t)(m0 + r) * DMODEL + koff + u * 8;
        else if (tile == 1) src = Alo + (size_t)(m0 + r) * DMODEL + koff + u * 8;
        else                src = Whi + (size_t)(n0 + r) * DMODEL + koff + u * 8;
        cp16(base + (uint32_t)(tile * TILE_B + r * ROWB + u * 16), src);
    }
    CP_COMMIT();
}

__global__ __launch_bounds__(512)
void hmma_gemm_wo(const __half* __restrict__ Ahi, const __half* __restrict__ Alo,
                  const __half* __restrict__ Whi, float* __restrict__ Cf)
{
    extern __shared__ char smem[];
    const uint32_t sb = smem_u32(smem);
    const int tid = threadIdx.x, wid = tid >> 5, lane = tid & 31;
    const int warp_m = wid >> 2, warp_n = wid & 3;
    const int n0 = blockIdx.x * 128, m0 = blockIdx.y * 128;

    float acc[2][4][4];
#pragma unroll
    for (int i = 0; i < 2; ++i)
#pragma unroll
        for (int j = 0; j < 4; ++j)
#pragma unroll
            for (int c = 0; c < 4; ++c) acc[i][j][c] = 0.f;

    uint32_t aoff[2], boff[2];
#pragma unroll
    for (int a = 0; a < 2; ++a)
        aoff[a] = (uint32_t)((warp_m * 32 + a * 16 + (lane & 15)) * ROWB
                             + ((lane >> 4) & 1) * 16);
#pragma unroll
    for (int p = 0; p < 2; ++p)
        boff[p] = (uint32_t)((warp_n * 32 + p * 16 + (lane & 7) + ((lane >> 4) << 3)) * ROWB
                             + ((lane >> 3) & 1) * 16);

    hmma_load_stage(sb, 0, 0, m0, n0, tid, Ahi, Alo, Whi);
    hmma_load_stage(sb, 1, 1, m0, n0, tid, Ahi, Alo, Whi);

    for (int kc = 0; kc < 32; ++kc) {
        if (kc >= 30) { CP_WAIT(0); } else { CP_WAIT(1); }
        __syncthreads();
        if (kc + 2 < 32)
            hmma_load_stage(sb, (kc + 2) % 3, kc + 2, m0, n0, tid, Ahi, Alo, Whi);
        const uint32_t stgb = sb + (uint32_t)(kc % 3) * STG_BYTES;
#pragma unroll
        for (int ks = 0; ks < 2; ++ks) {
            const uint32_t kb = (uint32_t)(ks * 32);
            uint32_t ahi[2][4], alo[2][4], bhi[2][4];
#pragma unroll
            for (int a = 0; a < 2; ++a) {
                ldsm4(ahi[a], stgb + aoff[a] + kb);
                ldsm4(alo[a], stgb + TILE_B + aoff[a] + kb);
            }
#pragma unroll
            for (int p = 0; p < 2; ++p)
                ldsm4(bhi[p], stgb + 2 * TILE_B + boff[p] + kb);
#pragma unroll
            for (int im = 0; im < 2; ++im)
#pragma unroll
                for (int in = 0; in < 4; ++in)
                    mma16816(acc[im][in], ahi[im], &bhi[in >> 1][(in & 1) * 2]);
#pragma unroll
            for (int im = 0; im < 2; ++im)
#pragma unroll
                for (int in = 0; in < 4; ++in)
                    mma16816(acc[im][in], alo[im], &bhi[in >> 1][(in & 1) * 2]);
        }
    }

#pragma unroll
    for (int im = 0; im < 2; ++im)
#pragma unroll
        for (int in = 0; in < 4; ++in) {
            const int nc = n0 + warp_n * 32 + in * 8 + (lane & 3) * 2;
#pragma unroll
            for (int half = 0; half < 2; ++half) {
                const int m = m0 + warp_m * 32 + im * 16 + (lane >> 2) + half * 8;
                *(float2*)(Cf + (size_t)m * DMODEL + nc) =
                    make_float2(acc[im][in][half * 2 + 0], acc[im][in][half * 2 + 1]);
            }
        }
}

// ================= seq HMMA GEMM: C[e,n] = sum_s wx[e,s] * B[n,s] =================
__device__ __forceinline__ void seq_load_stage(
    uint32_t sb, int stage, int k0, int brow0, int tid,
    const __half* __restrict__ Ah, const __half* __restrict__ Al,
    const __half* __restrict__ Bh, const __half* __restrict__ Bl)
{
    const uint32_t base = sb + (uint32_t)stage * SQ_STG;
#pragma unroll
    for (int it = 0; it < 2; ++it) {
        int i = it * 256 + tid;
        int hl = i >> 8, r = (i >> 2) & 63, u = i & 3;
        const __half* src = (hl ? Al : Ah) + (size_t)r * SEQ + k0 + u * 8;
        cp16(base + (uint32_t)(hl * SQ_ALO + r * ROWB + u * 16), src);
    }
#pragma unroll
    for (int it = 0; it < 4; ++it) {
        int i = it * 256 + tid;
        int hl = i >> 9, r = (i >> 2) & 127, u = i & 3;
        const __half* src = (hl ? Bl : Bh) + (size_t)(brow0 + r) * SEQ + k0 + u * 8;
        cp16(base + (uint32_t)(SQ_B + hl * SQ_BLO + r * ROWB + u * 16), src);
    }
    CP_COMMIT();
}

__global__ __launch_bounds__(256)
void seq_hmma(const __half* __restrict__ Bh, const __half* __restrict__ Bl,
              float* __restrict__ part)
{
    extern __shared__ char smem[];
    const uint32_t sb = smem_u32(smem);
    const int tid = threadIdx.x, wid = tid >> 5, lane = tid & 31;
    const int n0 = blockIdx.x * 128, b = blockIdx.y, seg = blockIdx.z;
    const int brow0 = b * DMODEL + n0;
    const int kbase = seg * 1024;

    float acc[4][2][4];
#pragma unroll
    for (int i = 0; i < 4; ++i)
#pragma unroll
        for (int j = 0; j < 2; ++j)
#pragma unroll
            for (int c = 0; c < 4; ++c) acc[i][j][c] = 0.f;

    uint32_t aoff[4];
#pragma unroll
    for (int atom = 0; atom < 4; ++atom)
        aoff[atom] = (uint32_t)((atom * 16 + (lane & 15)) * ROWB + ((lane >> 4) & 1) * 16);
    const uint32_t boff = (uint32_t)((wid * 16 + (lane & 7) + ((lane >> 4) << 3)) * ROWB
                                     + ((lane >> 3) & 1) * 16);

    const __half* Ah = g_wxhi;
    const __half* Al = g_wxlo;
    seq_load_stage(sb, 0, kbase + 0,  brow0, tid, Ah, Al, Bh, Bl);
    seq_load_stage(sb, 1, kbase + 32, brow0, tid, Ah, Al, Bh, Bl);

    for (int kc = 0; kc < 32; ++kc) {
        if (kc >= 30) { CP_WAIT(0); } else { CP_WAIT(1); }
        __syncthreads();
        if (kc + 2 < 32)
            seq_load_stage(sb, (kc + 2) % 3, kbase + (kc + 2) * 32, brow0, tid, Ah, Al, Bh, Bl);
        const uint32_t stgb = sb + (uint32_t)(kc % 3) * SQ_STG;
#pragma unroll
        for (int ks = 0; ks < 2; ++ks) {
            const uint32_t kb = (uint32_t)(ks * 32);
            uint32_t ahi[4][4], alo[4][4], bhi[4], blo[4];
#pragma unroll
            for (int atom = 0; atom < 4; ++atom) {
                ldsm4(ahi[atom], stgb + aoff[atom] + kb);
                ldsm4(alo[atom], stgb + SQ_ALO + aoff[atom] + kb);
            }
            ldsm4(bhi, stgb + SQ_B + boff + kb);
            ldsm4(blo, stgb + SQ_B + SQ_BLO + boff + kb);
#pragma unroll
            for (int im = 0; im < 4; ++im)
#pragma unroll
                for (int in = 0; in < 2; ++in)
                    mma16816(acc[im][in], ahi[im], &bhi[in * 2]);
#pragma unroll
            for (int im = 0; im < 4; ++im)
#pragma unroll
                for (int in = 0; in < 2; ++in)
                    mma16816(acc[im][in], alo[im], &bhi[in * 2]);
#pragma unroll
            for (int im = 0; im < 4; ++im)
#pragma unroll
                for (int in = 0; in < 2; ++in)
                    mma16816(acc[im][in], ahi[im], &blo[in * 2]);
        }
    }

    const size_t obase = (size_t)seg * (BATCH * DKC * DMODEL);
#pragma unroll
    for (int im = 0; im < 4; ++im)
#pragma unroll
        for (int in = 0; in < 2; ++in) {
            const int n = n0 + wid * 16 + in * 8 + (lane & 3) * 2;
#pragma unroll
            for (int half = 0; half < 2; ++half) {
                const int e = im * 16 + (lane >> 2) + half * 8;
                *(float2*)(part + obase + ((size_t)(b * DKC + e) << 10) + n) =
                    make_float2(acc[im][in][half * 2], acc[im][in][half * 2 + 1]);
            }
        }
}

__global__ void finish_kp(const float* __restrict__ wxb) {
    int idx = blockIdx.x * blockDim.x + threadIdx.x;
    float v = 0.f;
#pragma unroll
    for (int s = 0; s < NSEG; ++s) v += g_kp_part[s * (BATCH * DKC * DMODEL) + idx];
    g_kp[idx] = v + wxb[(idx >> 10) & 63];
}
__global__ void finish_T() {
    int idx = blockIdx.x * blockDim.x + threadIdx.x;
    float v = 0.f;
#pragma unroll
    for (int s = 0; s < NSEG; ++s) v += g_T_part[s * (BATCH * DKC * DMODEL) + idx];
    g_T[idx] = v;
}

// ================= qs: split-K SIMT GEMM (rows s<64 only) =================
__global__ __launch_bounds__(256)
void qs_gemm(const float* __restrict__ q, const float* __restrict__ wq)
{
    __shared__ float As[16][68];
    __shared__ float Bs[16][68];
    const int n0 = blockIdx.x * 64, b = blockIdx.y, seg = blockIdx.z;
    const int tid = threadIdx.x;
    const int ti = tid & 15, te = tid >> 4;
    const int lr = tid >> 2, lc = (tid & 3) * 4;

    float acc[4][4];
#pragma unroll
    for (int i = 0; i < 4; ++i)
#pragma unroll
        for (int j = 0; j < 4; ++j) acc[i][j] = 0.f;

    for (int kt = 0; kt < 16; ++kt) {
        const int k0 = seg * 256 + kt * 16;
        float4 pa = *(const float4*)(q  + ((size_t)b * SEQ + lr) * DMODEL + k0 + lc);
        float4 pb = *(const float4*)(wq + (size_t)(n0 + lr) * DMODEL + k0 + lc);
        As[lc + 0][lr] = pa.x; As[lc + 1][lr] = pa.y; As[lc + 2][lr] = pa.z; As[lc + 3][lr] = pa.w;
        Bs[lc + 0][lr] = pb.x; Bs[lc + 1][lr] = pb.y; Bs[lc + 2][lr] = pb.z; Bs[lc + 3][lr] = pb.w;
        __syncthreads();
#pragma unroll
        for (int kk = 0; kk < 16; ++kk) {
            float a[4], bb[4];
            *(float4*)a  = *(const float4*)&As[kk][te * 4];
            *(float4*)bb = *(const float4*)&Bs[kk][ti * 4];
#pragma unroll
            for (int i = 0; i < 4; ++i)
#pragma unroll
                for (int j = 0; j < 4; ++j)
                    acc[i][j] = fmaf(a[i], bb[j], acc[i][j]);
        }
        __syncthreads();
    }
    const size_t obase = (size_t)seg * (BATCH * DKC * DMODEL);
#pragma unroll
    for (int i = 0; i < 4; ++i)
#pragma unroll
        for (int j = 0; j < 4; ++j)
            g_qs_part[obase + ((size_t)(b * DKC + te * 4 + i) << 10) + n0 + ti * 4 + j] = acc[i][j];
}

__global__ void finish_qs() {
    int idx = blockIdx.x * blockDim.x + threadIdx.x;
    int m = idx >> 9, pr = idx & 511;
    float v0 = 0.f, v1 = 0.f;
#pragma unroll
    for (int s = 0; s < NSEG; ++s) {
        const float* p = g_qs_part + (size_t)s * (BATCH * DKC * DMODEL) + ((size_t)m << 10) + pr * 2;
        v0 += p[0]; v1 += p[1];
    }
    int sq = m & 63;
    int p = sq * HALF + pr;
    float cs = g_cos[p], sn = g_sin[p];
    g_qs[((size_t)m << 10) + pr * 2]     = v0 * cs - v1 * sn;
    g_qs[((size_t)m << 10) + pr * 2 + 1] = v1 * cs + v0 * sn;
}

// ================= vp[b,f,e] = sum_c wv[f,c]*T[b,e,c] + wxb[e] =================
__global__ __launch_bounds__(256)
void vp_kernel(const float* __restrict__ wv, const float* __restrict__ wxb)
{
    __shared__ float Wvs[64][68];
    __shared__ float Ts[64][68];
    const int f0 = blockIdx.x * 64;
    const int b  = blockIdx.y;
    const int tid = threadIdx.x;
    const int tf = tid & 15, te = tid >> 4;
    float acc[4][4];
#pragma unroll
    for (int a = 0; a < 4; ++a)
#pragma unroll
        for (int j = 0; j < 4; ++j) acc[a][j] = 0.f;

    for (int ch = 0; ch < 16; ++ch) {
        int cb = ch * 64;
#pragma unroll
        for (int r = 0; r < 16; ++r) {
            int l = r * 256 + tid;
            int row = l >> 6, col = l & 63;
            Wvs[row][col] = wv[(f0 + row) * DMODEL + cb + col];
            Ts[row][col]  = g_T[(b * DKC + row) * DMODEL + cb + col];
        }
        __syncthreads();
        for (int c = 0; c < 64; ++c) {
            float wf0 = Wvs[tf * 4 + 0][c], wf1 = Wvs[tf * 4 + 1][c];
            float wf2 = Wvs[tf * 4 + 2][c], wf3 = Wvs[tf * 4 + 3][c];
            float t0 = Ts[te * 4 + 0][c], t1 = Ts[te * 4 + 1][c];
            float t2 = Ts[te * 4 + 2][c], t3 = Ts[te * 4 + 3][c];
            acc[0][0] += wf0 * t0; acc[0][1] += wf0 * t1; acc[0][2] += wf0 * t2; acc[0][3] += wf0 * t3;
            acc[1][0] += wf1 * t0; acc[1][1] += wf1 * t1; acc[1][2] += wf1 * t2; acc[1][3] += wf1 * t3;
            acc[2][0] += wf2 * t0; acc[2][1] += wf2 * t1; acc[2][2] += wf2 * t2; acc[2][3] += wf2 * t3;
            acc[3][0] += wf3 * t0; acc[3][1] += wf3 * t1; acc[3][2] += wf3 * t2; acc[3][3] += wf3 * t3;
        }
        __syncthreads();
    }
#pragma unroll
    for (int a = 0; a < 4; ++a)
#pragma unroll
        for (int j = 0; j < 4; ++j) {
            int f = f0 + tf * 4 + a, e = te * 4 + j;
            g_vp[(b * DMODEL + f) * DKC + e] = acc[a][j] + wxb[e];
        }
}

// ================= tiny attention (s < 64 rows) =================
__global__ __launch_bounds__(64)
void attn_small()
{
    __shared__ float kps[64][64];
    __shared__ float vps[64][64];
    const int h = blockIdx.x, b = blockIdx.y, s = threadIdx.x;
#pragma unroll 4
    for (int e = 0; e < 64; ++e)
        kps[s][e] = g_kp[((size_t)(b * DKC + e) << 10) + h * DKC + s];
    for (int l = s; l < 4096; l += 64) {
        int d = l >> 6, e = l & 63;
        vps[d][e] = g_vp[(b * DMODEL + h * DKC + d) * DKC + e];
    }
    __syncthreads();

    float qv[64];
    const float* qp = g_qs + (b * DKC + s) * DMODEL + h * DKC;
#pragma unroll
    for (int d = 0; d < 64; d += 4) {
        float4 t = *(const float4*)(qp + d);
        qv[d] = t.x; qv[d + 1] = t.y; qv[d + 2] = t.z; qv[d + 3] = t.w;
    }
    const float lg0 = logf(1.0f / 32.0f);
    const float lg1 = logf(1.0f / 512.0f);
    const float gamma = 1.0f - expf(lg0 + (lg1 - lg0) * ((float)h / 15.0f));

    float sc[64];
#pragma unroll
    for (int e = 0; e < 64; ++e) {
        float a = 0.f;
#pragma unroll
        for (int d = 0; d < 64; ++d) a = fmaf(qv[d], kps[d][e], a);
        float dt = (e >= s) ? powf(gamma, (float)(e - s)) : 0.0f;
        sc[e] = a * dt;
    }
    float mx = -1e30f;
#pragma unroll
    for (int e = 0; e < 64; ++e) mx = fmaxf(mx, sc[e]);
    float sum = 0.f;
#pragma unroll
    for (int e = 0; e < 64; ++e) { sc[e] = expf(sc[e] - mx); sum += sc[e]; }
    float inv = 1.0f / sum;
#pragma unroll
    for (int f = 0; f < 64; ++f) {
        float a = 0.f;
#pragma unroll
        for (int e = 0; e < 64; ++e) a = fmaf(sc[e], vps[f][e], a);
        g_ysmall[(b * DKC + s) * DMODEL + h * DKC + f] = a * inv;
    }
}

// ================= group norm =================
__device__ __forceinline__ void gn4(float y[4], int d0,
                                    const float* gw, const float* gb, float out[4]) {
    float mu = (y[0] + y[1] + y[2] + y[3]) * 0.25f;
    float var = 0.f;
#pragma unroll
    for (int j = 0; j < 4; ++j) { float dd = y[j] - mu; var += dd * dd; }
    var *= 0.25f;
    float inv = rsqrtf(var + 1e-5f);
#pragma unroll
    for (int j = 0; j < 4; ++j) {
        int d = d0 + j;
        out[j] = (y[j] - mu) * inv * gw[d & 63] + gb[d & 63];
    }
}

__global__ void zbar_kernel(const float* __restrict__ gw, const float* __restrict__ gb) {
    int b = blockIdx.x, t = threadIdx.x;
    int d0 = t * 4;
    float y[4];
#pragma unroll
    for (int j = 0; j < 4; ++j) {
        const float* vp = g_vp + (b * DMODEL + d0 + j) * DKC;
        float s = 0.f;
#pragma unroll
        for (int e = 0; e < 64; ++e) s += vp[e];
        y[j] = s * (1.0f / 64.0f);
    }
    float o[4];
    gn4(y, d0, gw, gb, o);
#pragma unroll
    for (int j = 0; j < 4; ++j) g_zbar[b * DMODEL + d0 + j] = o[j];
}

__global__ void gn_small(const float* __restrict__ gw, const float* __restrict__ gb) {
    int row = blockIdx.x;
    int d0 = threadIdx.x * 4;
    float4 y4 = *(const float4*)(g_ysmall + row * DMODEL + d0);
    float y[4] = { y4.x, y4.y, y4.z, y4.w };
    float o[4];
    gn4(y, d0, gw, gb, o);
    *(float4*)(g_z + row * DMODEL + d0) = make_float4(o[0], o[1], o[2], o[3]);
}

// ================= launch =================
extern "C" void kernel_launch(void* const* d_in, const int* in_sizes, int n_in,
                              void* d_out, int out_size)
{
    const float* q   = (const float*)d_in[0];
    const float* k   = (const float*)d_in[1];
    const float* v   = (const float*)d_in[2];
    const float* wq  = (const float*)d_in[3];
    const float* wk  = (const float*)d_in[4];
    const float* wv  = (const float*)d_in[5];
    const float* wo  = (const float*)d_in[6];
    const float* wg  = (const float*)d_in[7];
    const float* wxw = (const float*)d_in[8];
    const float* wxb = (const float*)d_in[9];
    const float* gnw = (const float*)d_in[10];
    const float* gnb = (const float*)d_in[11];
    float* out = (float*)d_out;

    float *p_kpp, *p_tp;
    cudaGetSymbolAddress((void**)&p_kpp, g_kp_part);
    cudaGetSymbolAddress((void**)&p_tp,  g_T_part);

    int8_t *p_q8a, *p_q8b, *p_k8a, *p_k8b, *p_wk8a, *p_wk8b, *p_wg8a, *p_wg8b;
    cudaGetSymbolAddress((void**)&p_q8a,  g_q8a);  cudaGetSymbolAddress((void**)&p_q8b,  g_q8b);
    cudaGetSymbolAddress((void**)&p_k8a,  g_k8a);  cudaGetSymbolAddress((void**)&p_k8b,  g_k8b);
    cudaGetSymbolAddress((void**)&p_wk8a, g_wk8a); cudaGetSymbolAddress((void**)&p_wk8b, g_wk8b);
    cudaGetSymbolAddress((void**)&p_wg8a, g_wg8a); cudaGetSymbolAddress((void**)&p_wg8b, g_wg8b);

    __half *p_ahi, *p_alo, *p_wohi, *p_wolo, *p_wxhi, *p_wxlo;
    __half *p_kxThi, *p_kxTlo, *p_vThi, *p_vTlo;
    cudaGetSymbolAddress((void**)&p_ahi,  g_ahi);  cudaGetSymbolAddress((void**)&p_alo,  g_alo);
    cudaGetSymbolAddress((void**)&p_wohi, g_wohi); cudaGetSymbolAddress((void**)&p_wolo, g_wolo);
    cudaGetSymbolAddress((void**)&p_wxhi, g_wxhi); cudaGetSymbolAddress((void**)&p_wxlo, g_wxlo);
    cudaGetSymbolAddress((void**)&p_kxThi, g_kxThi); cudaGetSymbolAddress((void**)&p_kxTlo, g_kxTlo);
    cudaGetSymbolAddress((void**)&p_vThi,  g_vThi);  cudaGetSymbolAddress((void**)&p_vTlo,  g_vTlo);

    cudaFuncSetAttribute((const void*)imma_gemm<1>, cudaFuncAttributeMaxDynamicSharedMemorySize, SMEM_MAIN);
    cudaFuncSetAttribute((const void*)imma_gemm<2>, cudaFuncAttributeMaxDynamicSharedMemorySize, SMEM_MAIN);
    cudaFuncSetAttribute((const void*)hmma_gemm_wo, cudaFuncAttributeMaxDynamicSharedMemorySize, SMEM_MAIN);
    cudaFuncSetAttribute((const void*)seq_hmma, cudaFuncAttributeMaxDynamicSharedMemorySize, SMEM_SEQ);

    build_tables<<<(SEQ * HALF + 255) / 256, 256>>>();

    const int nact4 = MTOT * DMODEL / 4;
    const int nw4   = DMODEL * DMODEL / 4;
    const int nwx4  = DKC * SEQ / 4;

    // absmax + int8 quantization (q, k, wk, wg)
    reset_amax<<<1, 32>>>();
    absmax_kernel<<<1024, 256>>>(q,  nact4, 0);
    absmax_kernel<<<1024, 256>>>(k,  nact4, 1);
    absmax_kernel<<<256,  256>>>(wk, nw4,   2);
    absmax_kernel<<<256,  256>>>(wg, nw4,   3);
    quant8<<<nact4 / 256, 256>>>(q,  0, p_q8a,  p_q8b,  nact4);
    quant8<<<nact4 / 256, 256>>>(k,  1, p_k8a,  p_k8b,  nact4);
    quant8<<<nw4 / 256, 256>>>(wk, 2, p_wk8a, p_wk8b, nw4);
    quant8<<<nw4 / 256, 256>>>(wg, 3, p_wg8a, p_wg8b, nw4);

    // fp16 splits (wo weights, wx)
    split_half<<<nw4 / 256, 256>>>(wo,  p_wohi, p_wolo, nw4);
    split_half<<<nwx4 / 256, 256>>>(wxw, p_wxhi, p_wxlo, nwx4);

    vt_split<<<dim3(SEQ / 64, DMODEL / 64, BATCH), 256>>>(v, p_vThi, p_vTlo);

    // keyxT = xpos(k @ wk^T)^T fp16 hi/lo, via int8 IMMA
    imma_gemm<1><<<dim3(8, 128), 512, SMEM_MAIN>>>(p_k8a, p_k8b, p_wk8a, p_wk8b,
                                                   1, 2, p_kxThi, p_kxTlo);
    // qs = xpos(q @ wq^T) rows s<64
    qs_gemm<<<dim3(16, BATCH, NSEG), 256>>>(q, wq);
    finish_qs<<<(BATCH * DKC * HALF) / 256, 256>>>();

    // kp / T seq contractions via fp16 HMMA
    seq_hmma<<<dim3(8, BATCH, NSEG), 256, SMEM_SEQ>>>(p_kxThi, p_kxTlo, p_kpp);
    seq_hmma<<<dim3(8, BATCH, NSEG), 256, SMEM_SEQ>>>(p_vThi,  p_vTlo,  p_tp);
    finish_kp<<<(BATCH * DKC * DMODEL) / 256, 256>>>(wxb);
    finish_T <<<(BATCH * DKC * DMODEL) / 256, 256>>>();

    vp_kernel<<<dim3(16, BATCH), 256>>>(wv, wxb);
    attn_small<<<dim3(HEADS, BATCH), 64>>>();
    zbar_kernel<<<BATCH, 256>>>(gnw, gnb);
    gn_small<<<BATCH * DKC, 256>>>(gnw, gnb);

    // act = silu((q @ wg^T) * z) -> fp16 hi/lo, via int8 IMMA
    imma_gemm<2><<<dim3(8, 128), 512, SMEM_MAIN>>>(p_q8a, p_q8b, p_wg8a, p_wg8b,
                                                   0, 3, p_ahi, p_alo);
    // out = act @ wo^T, fp16 2-pass HMMA (act is heavy-tailed; keep relative precision)
    hmma_gemm_wo<<<dim3(8, 128), 512, SMEM_MAIN>>>(p_ahi, p_alo, p_wohi, out);
}

// round 9
// speedup vs baseline: 2.1642x; 2.1642x over previous
#include <cuda_runtime.h>
#include <cuda_fp16.h>
#include <math.h>
#include <stdint.h>

#define BATCH   4
#define SEQ     4096
#define DMODEL  1024
#define HEADS   16
#define DKC     64
#define HALF    512
#define NSEG    4
#define MTOT    (BATCH * SEQ)    /* 16384 */

// ---------------- scratch (device globals; no allocations) ----------------
__device__ float g_cos[SEQ * HALF];
__device__ float g_sin[SEQ * HALF];
__device__ float g_qs[BATCH * DKC * DMODEL];
__device__ float g_qs_part[NSEG * BATCH * DKC * DMODEL];
__device__ float g_kp_part[NSEG * BATCH * DKC * DMODEL];
__device__ float g_T_part [NSEG * BATCH * DKC * DMODEL];
__device__ float g_kp[BATCH * DKC * DMODEL];            // kp[b][e][d]
__device__ float g_T [BATCH * DKC * DMODEL];            // T[b][e][c]
__device__ float g_vp[BATCH * DMODEL * DKC];            // vp[b][f][e]
__device__ float g_ysmall[BATCH * DKC * DMODEL];
__device__ float g_z[BATCH * DKC * DMODEL];
__device__ float g_zbar[BATCH * DMODEL];

// fp16 split operands
__device__ __half g_qhi[MTOT * DMODEL];                          // q hi (wg 1-pass)
__device__ __half g_khi[MTOT * DMODEL], g_klo[MTOT * DMODEL];    // k hi/lo (wk 2-pass)
__device__ __half g_ahi[MTOT * DMODEL], g_alo[MTOT * DMODEL];    // silu(gate) hi/lo
__device__ __half g_wkhi[DMODEL * DMODEL];
__device__ __half g_wghi[DMODEL * DMODEL];
__device__ __half g_wohi[DMODEL * DMODEL];
__device__ __half g_wxhi[DKC * SEQ], g_wxlo[DKC * SEQ];
// transposed seq-major operands [b*DMODEL + d][SEQ]
__device__ __half g_kxThi[BATCH * DMODEL * SEQ], g_kxTlo[BATCH * DMODEL * SEQ];
__device__ __half g_vThi [BATCH * DMODEL * SEQ], g_vTlo [BATCH * DMODEL * SEQ];

// ================= PTX helpers =================
__device__ __forceinline__ uint32_t smem_u32(const void* p) {
    uint32_t a;
    asm("{ .reg .u64 t; cvta.to.shared.u64 t, %1; cvt.u32.u64 %0, t; }" : "=r"(a) : "l"(p));
    return a;
}
__device__ __forceinline__ void cp16(uint32_t dst, const void* src) {
    asm volatile("cp.async.cg.shared.global [%0], [%1], 16;" :: "r"(dst), "l"(src) : "memory");
}
#define CP_COMMIT() asm volatile("cp.async.commit_group;" ::: "memory")
#define CP_WAIT(N)  asm volatile("cp.async.wait_group %0;" :: "n"(N) : "memory")

__device__ __forceinline__ void ldsm4(uint32_t* r, uint32_t addr) {
    asm volatile("ldmatrix.sync.aligned.m8n8.x4.shared.b16 {%0,%1,%2,%3}, [%4];"
                 : "=r"(r[0]), "=r"(r[1]), "=r"(r[2]), "=r"(r[3]) : "r"(addr));
}
__device__ __forceinline__ void mma16816(float* d, const uint32_t* a, const uint32_t* b) {
    asm volatile("mma.sync.aligned.m16n8k16.row.col.f32.f16.f16.f32 "
                 "{%0,%1,%2,%3}, {%4,%5,%6,%7}, {%8,%9}, {%0,%1,%2,%3};"
                 : "+f"(d[0]), "+f"(d[1]), "+f"(d[2]), "+f"(d[3])
                 : "r"(a[0]), "r"(a[1]), "r"(a[2]), "r"(a[3]), "r"(b[0]), "r"(b[1]));
}

// SMEM: rows padded to 80B; tiles: 0=Ahi 1=Alo 2=Whi ; 3 stages
#define ROWB      80
#define TILE_B    10240
#define STG_BYTES 40960
#define SMEM_MAIN (3 * STG_BYTES)   /* 122880 */
#define TP_PAD    136

// seq GEMM SMEM
#define SQ_STG    30720
#define SQ_ALO    5120
#define SQ_B      10240
#define SQ_BLO    10240
#define SMEM_SEQ  (3 * SQ_STG)

// ================= xpos tables =================
__global__ void build_tables() {
    int idx = blockIdx.x * blockDim.x + threadIdx.x;
    if (idx >= SEQ * HALF) return;
    int s = idx / HALF, i = idx % HALF;
    float sv    = (2.0f * i + 0.4f * DMODEL) / (1.4f * DMODEL);
    float scale = powf(sv, (float)s / 512.0f);
    float invf  = powf(10000.0f, -(float)i / (float)HALF);
    float ang   = (float)s * invf;
    g_cos[idx] = cosf(ang) * scale;
    g_sin[idx] = sinf(ang) * scale;
}

// ================= fp32 -> fp16 splits =================
__global__ void split_half(const float* __restrict__ x, __half* __restrict__ hi,
                           __half* __restrict__ lo, int n4) {
    int i = blockIdx.x * blockDim.x + threadIdx.x;
    if (i >= n4) return;
    float4 v = ((const float4*)x)[i];
    __half h0 = __float2half(v.x), h1 = __float2half(v.y);
    __half h2 = __float2half(v.z), h3 = __float2half(v.w);
    __half l0 = __float2half(v.x - __half2float(h0));
    __half l1 = __float2half(v.y - __half2float(h1));
    __half l2 = __float2half(v.z - __half2float(h2));
    __half l3 = __float2half(v.w - __half2float(h3));
    __half2* ph = (__half2*)(hi) + i * 2;
    __half2* pl = (__half2*)(lo) + i * 2;
    ph[0] = __half2(h0, h1); ph[1] = __half2(h2, h3);
    pl[0] = __half2(l0, l1); pl[1] = __half2(l2, l3);
}
__global__ void split_hi(const float* __restrict__ x, __half* __restrict__ hi, int n4) {
    int i = blockIdx.x * blockDim.x + threadIdx.x;
    if (i >= n4) return;
    float4 v = ((const float4*)x)[i];
    __half2* ph = (__half2*)(hi) + i * 2;
    ph[0] = __half2(__float2half(v.x), __float2half(v.y));
    ph[1] = __half2(__float2half(v.z), __float2half(v.w));
}

// ================= v -> vT hi/lo (transpose + split) =================
__global__ __launch_bounds__(256)
void vt_split(const float* __restrict__ v, __half* __restrict__ th,
              __half* __restrict__ tl)
{
    __shared__ float ts[64][65];
    const int s0 = blockIdx.x * 64, c0 = blockIdx.y * 64, b = blockIdx.z;
    const int tid = threadIdx.x;
    const int r = tid >> 2, quad = tid & 3;
#pragma unroll
    for (int j = 0; j < 4; ++j) {
        int col = quad * 16 + j * 4;
        float4 x = *(const float4*)(v + ((size_t)b * SEQ + s0 + r) * DMODEL + c0 + col);
        ts[r][col] = x.x; ts[r][col + 1] = x.y; ts[r][col + 2] = x.z; ts[r][col + 3] = x.w;
    }
    __syncthreads();
    uint4 hv[2], lv[2];
    __half* hh = (__half*)hv;
    __half* ll = (__half*)lv;
#pragma unroll
    for (int j = 0; j < 16; ++j) {
        float x = ts[quad * 16 + j][r];
        hh[j] = __float2half(x);
        ll[j] = __float2half(x - __half2float(hh[j]));
    }
    size_t row = ((size_t)b * DMODEL + c0 + r) * SEQ + s0 + quad * 16;
    *(uint4*)(th + row) = hv[0]; *(uint4*)(th + row + 8) = hv[1];
    *(uint4*)(tl + row) = lv[0]; *(uint4*)(tl + row + 8) = lv[1];
}

// ================= HMMA split GEMM: C[m,n] = sum_k A[m,k]*W[n,k] =================
// CTA 128x128, 16 warps (4x4), warp tile 32x32, K chunks of 32, 3-stage ring.
// PASSES=2: AhWh + AlWh ; PASSES=1: AhWh only.
// EPI: 0 fp32 out ; 1 xpos -> keyxT fp16 hi/lo transposed ; 2 gate*z+silu -> fp16 hi/lo.
template<int PASSES>
__device__ __forceinline__ void load_stage512(
    uint32_t sb, int slot, int kc, int m0, int n0, int tid,
    const __half* __restrict__ Ahi, const __half* __restrict__ Alo,
    const __half* __restrict__ Whi)
{
    const uint32_t base = sb + (uint32_t)slot * STG_BYTES;
    const int koff = kc * 32;
    const int NT = PASSES + 1;
#pragma unroll
    for (int it = 0; it < NT; ++it) {
        int i = it * 512 + tid;
        int t = i >> 9;
        int tile = (PASSES == 1) ? (t * 2) : t;   // P=1: tiles {0,2}
        int r = (i >> 2) & 127, u = i & 3;
        const __half* src;
        if      (tile == 0) src = Ahi + (size_t)(m0 + r) * DMODEL + koff + u * 8;
        else if (tile == 1) src = Alo + (size_t)(m0 + r) * DMODEL + koff + u * 8;
        else                src = Whi + (size_t)(n0 + r) * DMODEL + koff + u * 8;
        cp16(base + (uint32_t)(tile * TILE_B + r * ROWB + u * 16), src);
    }
    CP_COMMIT();
}

template<int EPI, int PASSES>
__global__ __launch_bounds__(512)
void hmma_gemm(const __half* __restrict__ Ahi, const __half* __restrict__ Alo,
               const __half* __restrict__ Whi,
               float* __restrict__ Cf,
               __half* __restrict__ Chi, __half* __restrict__ Clo)
{
    extern __shared__ char smem[];
    const uint32_t sb = smem_u32(smem);
    const int tid = threadIdx.x, wid = tid >> 5, lane = tid & 31;
    const int warp_m = wid >> 2, warp_n = wid & 3;
    const int n0 = blockIdx.x * 128, m0 = blockIdx.y * 128;

    float acc[2][4][4];
#pragma unroll
    for (int i = 0; i < 2; ++i)
#pragma unroll
        for (int j = 0; j < 4; ++j)
#pragma unroll
            for (int c = 0; c < 4; ++c) acc[i][j][c] = 0.f;

    uint32_t aoff[2], boff[2];
#pragma unroll
    for (int a = 0; a < 2; ++a)
        aoff[a] = (uint32_t)((warp_m * 32 + a * 16 + (lane & 15)) * ROWB
                             + ((lane >> 4) & 1) * 16);
#pragma unroll
    for (int p = 0; p < 2; ++p)
        boff[p] = (uint32_t)((warp_n * 32 + p * 16 + (lane & 7) + ((lane >> 4) << 3)) * ROWB
                             + ((lane >> 3) & 1) * 16);

    load_stage512<PASSES>(sb, 0, 0, m0, n0, tid, Ahi, Alo, Whi);
    load_stage512<PASSES>(sb, 1, 1, m0, n0, tid, Ahi, Alo, Whi);

    for (int kc = 0; kc < 32; ++kc) {
        if (kc >= 30) { CP_WAIT(0); } else { CP_WAIT(1); }
        __syncthreads();
        if (kc + 2 < 32)
            load_stage512<PASSES>(sb, (kc + 2) % 3, kc + 2, m0, n0, tid, Ahi, Alo, Whi);
        const uint32_t stgb = sb + (uint32_t)(kc % 3) * STG_BYTES;
#pragma unroll
        for (int ks = 0; ks < 2; ++ks) {
            const uint32_t kb = (uint32_t)(ks * 32);
            uint32_t ahi[2][4], alo[2][4], bhi[2][4];
#pragma unroll
            for (int a = 0; a < 2; ++a) {
                ldsm4(ahi[a], stgb + aoff[a] + kb);
                if (PASSES >= 2) ldsm4(alo[a], stgb + TILE_B + aoff[a] + kb);
            }
#pragma unroll
            for (int p = 0; p < 2; ++p)
                ldsm4(bhi[p], stgb + 2 * TILE_B + boff[p] + kb);
#pragma unroll
            for (int im = 0; im < 2; ++im)
#pragma unroll
                for (int in = 0; in < 4; ++in)
                    mma16816(acc[im][in], ahi[im], &bhi[in >> 1][(in & 1) * 2]);
            if (PASSES >= 2) {
#pragma unroll
                for (int im = 0; im < 2; ++im)
#pragma unroll
                    for (int in = 0; in < 4; ++in)
                        mma16816(acc[im][in], alo[im], &bhi[in >> 1][(in & 1) * 2]);
            }
        }
    }

    // -------- epilogue --------
    if (EPI == 1) {
        __syncthreads();   // stage slots reused as transpose buffer
        __half* sh = (__half*)smem;
        __half* sl = sh + 128 * TP_PAD;
#pragma unroll
        for (int im = 0; im < 2; ++im)
#pragma unroll
            for (int in = 0; in < 4; ++in) {
                const int dl = warp_n * 32 + in * 8 + (lane & 3) * 2;
                const int nc = n0 + dl;
#pragma unroll
                for (int half = 0; half < 2; ++half) {
                    const int ml = warp_m * 32 + im * 16 + (lane >> 2) + half * 8;
                    const int s = (m0 + ml) & (SEQ - 1);
                    float v0 = acc[im][in][half * 2 + 0];
                    float v1 = acc[im][in][half * 2 + 1];
                    int p = s * HALF + (nc >> 1);
                    float cs = g_cos[p], sn = g_sin[p];
                    float o0 = v0 * cs - v1 * sn;
                    float o1 = v1 * cs + v0 * sn;
                    __half h0 = __float2half(o0), h1 = __float2half(o1);
                    __half l0 = __float2half(o0 - __half2float(h0));
                    __half l1 = __float2half(o1 - __half2float(h1));
                    sh[dl * TP_PAD + ml] = h0; sh[(dl + 1) * TP_PAD + ml] = h1;
                    sl[dl * TP_PAD + ml] = l0; sl[(dl + 1) * TP_PAD + ml] = l1;
                }
            }
        __syncthreads();
        const int s0 = m0 & (SEQ - 1), bb = m0 >> 12;
#pragma unroll
        for (int it = 0; it < 4; ++it) {
            int slot = it * 512 + tid;
            int dr = slot >> 4;
            int sc = (slot & 15) * 8;
            size_t grow = ((size_t)(bb * DMODEL + n0 + dr)) * SEQ + s0 + sc;
            *(uint4*)(Chi + grow) = *(uint4*)(sh + dr * TP_PAD + sc);
            *(uint4*)(Clo + grow) = *(uint4*)(sl + dr * TP_PAD + sc);
        }
        return;
    }
#pragma unroll
    for (int im = 0; im < 2; ++im) {
#pragma unroll
        for (int in = 0; in < 4; ++in) {
            const int nc = n0 + warp_n * 32 + in * 8 + (lane & 3) * 2;
#pragma unroll
            for (int half = 0; half < 2; ++half) {
                const int m = m0 + warp_m * 32 + im * 16 + (lane >> 2) + half * 8;
                const int s = m & (SEQ - 1);
                const int bb = m >> 12;
                float v0 = acc[im][in][half * 2 + 0];
                float v1 = acc[im][in][half * 2 + 1];
                if (EPI == 0) {
                    *(float2*)(Cf + (size_t)m * DMODEL + nc) = make_float2(v0, v1);
                } else {
                    const float* zr = (s < DKC) ? (g_z + (bb * DKC + s) * DMODEL)
                                                : (g_zbar + bb * DMODEL);
                    float a0 = v0 * zr[nc];
                    float a1 = v1 * zr[nc + 1];
                    a0 = a0 / (1.f + expf(-a0));
                    a1 = a1 / (1.f + expf(-a1));
                    __half h0 = __float2half(a0), h1 = __float2half(a1);
                    __half l0 = __float2half(a0 - __half2float(h0));
                    __half l1 = __float2half(a1 - __half2float(h1));
                    *(__half2*)(Chi + (size_t)m * DMODEL + nc) = __half2(h0, h1);
                    *(__half2*)(Clo + (size_t)m * DMODEL + nc) = __half2(l0, l1);
                }
            }
        }
    }
}

// ================= seq HMMA GEMM: C[e,n] = sum_s wx[e,s] * B[n,s] =================
__device__ __forceinline__ void seq_load_stage(
    uint32_t sb, int stage, int k0, int brow0, int tid,
    const __half* __restrict__ Ah, const __half* __restrict__ Al,
    const __half* __restrict__ Bh, const __half* __restrict__ Bl)
{
    const uint32_t base = sb + (uint32_t)stage * SQ_STG;
#pragma unroll
    for (int it = 0; it < 2; ++it) {
        int i = it * 256 + tid;
        int hl = i >> 8, r = (i >> 2) & 63, u = i & 3;
        const __half* src = (hl ? Al : Ah) + (size_t)r * SEQ + k0 + u * 8;
        cp16(base + (uint32_t)(hl * SQ_ALO + r * ROWB + u * 16), src);
    }
#pragma unroll
    for (int it = 0; it < 4; ++it) {
        int i = it * 256 + tid;
        int hl = i >> 9, r = (i >> 2) & 127, u = i & 3;
        const __half* src = (hl ? Bl : Bh) + (size_t)(brow0 + r) * SEQ + k0 + u * 8;
        cp16(base + (uint32_t)(SQ_B + hl * SQ_BLO + r * ROWB + u * 16), src);
    }
    CP_COMMIT();
}

__global__ __launch_bounds__(256)
void seq_hmma(const __half* __restrict__ Bh, const __half* __restrict__ Bl,
              float* __restrict__ part)
{
    extern __shared__ char smem[];
    const uint32_t sb = smem_u32(smem);
    const int tid = threadIdx.x, wid = tid >> 5, lane = tid & 31;
    const int n0 = blockIdx.x * 128, b = blockIdx.y, seg = blockIdx.z;
    const int brow0 = b * DMODEL + n0;
    const int kbase = seg * 1024;

    float acc[4][2][4];
#pragma unroll
    for (int i = 0; i < 4; ++i)
#pragma unroll
        for (int j = 0; j < 2; ++j)
#pragma unroll
            for (int c = 0; c < 4; ++c) acc[i][j][c] = 0.f;

    uint32_t aoff[4];
#pragma unroll
    for (int atom = 0; atom < 4; ++atom)
        aoff[atom] = (uint32_t)((atom * 16 + (lane & 15)) * ROWB + ((lane >> 4) & 1) * 16);
    const uint32_t boff = (uint32_t)((wid * 16 + (lane & 7) + ((lane >> 4) << 3)) * ROWB
                                     + ((lane >> 3) & 1) * 16);

    const __half* Ah = g_wxhi;
    const __half* Al = g_wxlo;
    seq_load_stage(sb, 0, kbase + 0,  brow0, tid, Ah, Al, Bh, Bl);
    seq_load_stage(sb, 1, kbase + 32, brow0, tid, Ah, Al, Bh, Bl);

    for (int kc = 0; kc < 32; ++kc) {
        if (kc >= 30) { CP_WAIT(0); } else { CP_WAIT(1); }
        __syncthreads();
        if (kc + 2 < 32)
            seq_load_stage(sb, (kc + 2) % 3, kbase + (kc + 2) * 32, brow0, tid, Ah, Al, Bh, Bl);
        const uint32_t stgb = sb + (uint32_t)(kc % 3) * SQ_STG;
#pragma unroll
        for (int ks = 0; ks < 2; ++ks) {
            const uint32_t kb = (uint32_t)(ks * 32);
            uint32_t ahi[4][4], alo[4][4], bhi[4], blo[4];
#pragma unroll
            for (int atom = 0; atom < 4; ++atom) {
                ldsm4(ahi[atom], stgb + aoff[atom] + kb);
                ldsm4(alo[atom], stgb + SQ_ALO + aoff[atom] + kb);
            }
            ldsm4(bhi, stgb + SQ_B + boff + kb);
            ldsm4(blo, stgb + SQ_B + SQ_BLO + boff + kb);
#pragma unroll
            for (int im = 0; im < 4; ++im)
#pragma unroll
                for (int in = 0; in < 2; ++in)
                    mma16816(acc[im][in], ahi[im], &bhi[in * 2]);
#pragma unroll
            for (int im = 0; im < 4; ++im)
#pragma unroll
                for (int in = 0; in < 2; ++in)
                    mma16816(acc[im][in], alo[im], &bhi[in * 2]);
#pragma unroll
            for (int im = 0; im < 4; ++im)
#pragma unroll
                for (int in = 0; in < 2; ++in)
                    mma16816(acc[im][in], ahi[im], &blo[in * 2]);
        }
    }

    const size_t obase = (size_t)seg * (BATCH * DKC * DMODEL);
#pragma unroll
    for (int im = 0; im < 4; ++im)
#pragma unroll
        for (int in = 0; in < 2; ++in) {
            const int n = n0 + wid * 16 + in * 8 + (lane & 3) * 2;
#pragma unroll
            for (int half = 0; half < 2; ++half) {
                const int e = im * 16 + (lane >> 2) + half * 8;
                *(float2*)(part + obase + ((size_t)(b * DKC + e) << 10) + n) =
                    make_float2(acc[im][in][half * 2], acc[im][in][half * 2 + 1]);
            }
        }
}

__global__ void finish_kp(const float* __restrict__ wxb) {
    int idx = blockIdx.x * blockDim.x + threadIdx.x;
    float v = 0.f;
#pragma unroll
    for (int s = 0; s < NSEG; ++s) v += g_kp_part[s * (BATCH * DKC * DMODEL) + idx];
    g_kp[idx] = v + wxb[(idx >> 10) & 63];
}
__global__ void finish_T() {
    int idx = blockIdx.x * blockDim.x + threadIdx.x;
    float v = 0.f;
#pragma unroll
    for (int s = 0; s < NSEG; ++s) v += g_T_part[s * (BATCH * DKC * DMODEL) + idx];
    g_T[idx] = v;
}

// ================= qs: split-K SIMT GEMM (rows s<64 only) =================
__global__ __launch_bounds__(256)
void qs_gemm(const float* __restrict__ q, const float* __restrict__ wq)
{
    __shared__ float As[16][68];
    __shared__ float Bs[16][68];
    const int n0 = blockIdx.x * 64, b = blockIdx.y, seg = blockIdx.z;
    const int tid = threadIdx.x;
    const int ti = tid & 15, te = tid >> 4;
    const int lr = tid >> 2, lc = (tid & 3) * 4;

    float acc[4][4];
#pragma unroll
    for (int i = 0; i < 4; ++i)
#pragma unroll
        for (int j = 0; j < 4; ++j) acc[i][j] = 0.f;

    for (int kt = 0; kt < 16; ++kt) {
        const int k0 = seg * 256 + kt * 16;
        float4 pa = *(const float4*)(q  + ((size_t)b * SEQ + lr) * DMODEL + k0 + lc);
        float4 pb = *(const float4*)(wq + (size_t)(n0 + lr) * DMODEL + k0 + lc);
        As[lc + 0][lr] = pa.x; As[lc + 1][lr] = pa.y; As[lc + 2][lr] = pa.z; As[lc + 3][lr] = pa.w;
        Bs[lc + 0][lr] = pb.x; Bs[lc + 1][lr] = pb.y; Bs[lc + 2][lr] = pb.z; Bs[lc + 3][lr] = pb.w;
        __syncthreads();
#pragma unroll
        for (int kk = 0; kk < 16; ++kk) {
            float a[4], bb[4];
            *(float4*)a  = *(const float4*)&As[kk][te * 4];
            *(float4*)bb = *(const float4*)&Bs[kk][ti * 4];
#pragma unroll
            for (int i = 0; i < 4; ++i)
#pragma unroll
                for (int j = 0; j < 4; ++j)
                    acc[i][j] = fmaf(a[i], bb[j], acc[i][j]);
        }
        __syncthreads();
    }
    const size_t obase = (size_t)seg * (BATCH * DKC * DMODEL);
#pragma unroll
    for (int i = 0; i < 4; ++i)
#pragma unroll
        for (int j = 0; j < 4; ++j)
            g_qs_part[obase + ((size_t)(b * DKC + te * 4 + i) << 10) + n0 + ti * 4 + j] = acc[i][j];
}

__global__ void finish_qs() {
    int idx = blockIdx.x * blockDim.x + threadIdx.x;
    int m = idx >> 9, pr = idx & 511;
    float v0 = 0.f, v1 = 0.f;
#pragma unroll
    for (int s = 0; s < NSEG; ++s) {
        const float* p = g_qs_part + (size_t)s * (BATCH * DKC * DMODEL) + ((size_t)m << 10) + pr * 2;
        v0 += p[0]; v1 += p[1];
    }
    int sq = m & 63;
    int p = sq * HALF + pr;
    float cs = g_cos[p], sn = g_sin[p];
    g_qs[((size_t)m << 10) + pr * 2]     = v0 * cs - v1 * sn;
    g_qs[((size_t)m << 10) + pr * 2 + 1] = v1 * cs + v0 * sn;
}

// ================= vp[b,f,e] = sum_c wv[f,c]*T[b,e,c] + wxb[e] =================
__global__ __launch_bounds__(256)
void vp_kernel(const float* __restrict__ wv, const float* __restrict__ wxb)
{
    __shared__ float Wvs[64][68];
    __shared__ float Ts[64][68];
    const int f0 = blockIdx.x * 64;
    const int b  = blockIdx.y;
    const int tid = threadIdx.x;
    const int tf = tid & 15, te = tid >> 4;
    float acc[4][4];
#pragma unroll
    for (int a = 0; a < 4; ++a)
#pragma unroll
        for (int j = 0; j < 4; ++j) acc[a][j] = 0.f;

    for (int ch = 0; ch < 16; ++ch) {
        int cb = ch * 64;
#pragma unroll
        for (int r = 0; r < 16; ++r) {
            int l = r * 256 + tid;
            int row = l >> 6, col = l & 63;
            Wvs[row][col] = wv[(f0 + row) * DMODEL + cb + col];
            Ts[row][col]  = g_T[(b * DKC + row) * DMODEL + cb + col];
        }
        __syncthreads();
        for (int c = 0; c < 64; ++c) {
            float wf0 = Wvs[tf * 4 + 0][c], wf1 = Wvs[tf * 4 + 1][c];
            float wf2 = Wvs[tf * 4 + 2][c], wf3 = Wvs[tf * 4 + 3][c];
            float t0 = Ts[te * 4 + 0][c], t1 = Ts[te * 4 + 1][c];
            float t2 = Ts[te * 4 + 2][c], t3 = Ts[te * 4 + 3][c];
            acc[0][0] += wf0 * t0; acc[0][1] += wf0 * t1; acc[0][2] += wf0 * t2; acc[0][3] += wf0 * t3;
            acc[1][0] += wf1 * t0; acc[1][1] += wf1 * t1; acc[1][2] += wf1 * t2; acc[1][3] += wf1 * t3;
            acc[2][0] += wf2 * t0; acc[2][1] += wf2 * t1; acc[2][2] += wf2 * t2; acc[2][3] += wf2 * t3;
            acc[3][0] += wf3 * t0; acc[3][1] += wf3 * t1; acc[3][2] += wf3 * t2; acc[3][3] += wf3 * t3;
        }
        __syncthreads();
    }
#pragma unroll
    for (int a = 0; a < 4; ++a)
#pragma unroll
        for (int j = 0; j < 4; ++j) {
            int f = f0 + tf * 4 + a, e = te * 4 + j;
            g_vp[(b * DMODEL + f) * DKC + e] = acc[a][j] + wxb[e];
        }
}

// ================= tiny attention (s < 64 rows) =================
__global__ __launch_bounds__(64)
void attn_small()
{
    __shared__ float kps[64][64];
    __shared__ float vps[64][64];
    const int h = blockIdx.x, b = blockIdx.y, s = threadIdx.x;
#pragma unroll 4
    for (int e = 0; e < 64; ++e)
        kps[s][e] = g_kp[((size_t)(b * DKC + e) << 10) + h * DKC + s];
    for (int l = s; l < 4096; l += 64) {
        int d = l >> 6, e = l & 63;
        vps[d][e] = g_vp[(b * DMODEL + h * DKC + d) * DKC + e];
    }
    __syncthreads();

    float qv[64];
    const float* qp = g_qs + (b * DKC + s) * DMODEL + h * DKC;
#pragma unroll
    for (int d = 0; d < 64; d += 4) {
        float4 t = *(const float4*)(qp + d);
        qv[d] = t.x; qv[d + 1] = t.y; qv[d + 2] = t.z; qv[d + 3] = t.w;
    }
    const float lg0 = logf(1.0f / 32.0f);
    const float lg1 = logf(1.0f / 512.0f);
    const float gamma = 1.0f - expf(lg0 + (lg1 - lg0) * ((float)h / 15.0f));

    float sc[64];
#pragma unroll
    for (int e = 0; e < 64; ++e) {
        float a = 0.f;
#pragma unroll
        for (int d = 0; d < 64; ++d) a = fmaf(qv[d], kps[d][e], a);
        float dt = (e >= s) ? powf(gamma, (float)(e - s)) : 0.0f;
        sc[e] = a * dt;
    }
    float mx = -1e30f;
#pragma unroll
    for (int e = 0; e < 64; ++e) mx = fmaxf(mx, sc[e]);
    float sum = 0.f;
#pragma unroll
    for (int e = 0; e < 64; ++e) { sc[e] = expf(sc[e] - mx); sum += sc[e]; }
    float inv = 1.0f / sum;
#pragma unroll
    for (int f = 0; f < 64; ++f) {
        float a = 0.f;
#pragma unroll
        for (int e = 0; e < 64; ++e) a = fmaf(sc[e], vps[f][e], a);
        g_ysmall[(b * DKC + s) * DMODEL + h * DKC + f] = a * inv;
    }
}

// ================= group norm =================
__device__ __forceinline__ void gn4(float y[4], int d0,
                                    const float* gw, const float* gb, float out[4]) {
    float mu = (y[0] + y[1] + y[2] + y[3]) * 0.25f;
    float var = 0.f;
#pragma unroll
    for (int j = 0; j < 4; ++j) { float dd = y[j] - mu; var += dd * dd; }
    var *= 0.25f;
    float inv = rsqrtf(var + 1e-5f);
#pragma unroll
    for (int j = 0; j < 4; ++j) {
        int d = d0 + j;
        out[j] = (y[j] - mu) * inv * gw[d & 63] + gb[d & 63];
    }
}

__global__ void zbar_kernel(const float* __restrict__ gw, const float* __restrict__ gb) {
    int b = blockIdx.x, t = threadIdx.x;
    int d0 = t * 4;
    float y[4];
#pragma unroll
    for (int j = 0; j < 4; ++j) {
        const float* vp = g_vp + (b * DMODEL + d0 + j) * DKC;
        float s = 0.f;
#pragma unroll
        for (int e = 0; e < 64; ++e) s += vp[e];
        y[j] = s * (1.0f / 64.0f);
    }
    float o[4];
    gn4(y, d0, gw, gb, o);
#pragma unroll
    for (int j = 0; j < 4; ++j) g_zbar[b * DMODEL + d0 + j] = o[j];
}

__global__ void gn_small(const float* __restrict__ gw, const float* __restrict__ gb) {
    int row = blockIdx.x;
    int d0 = threadIdx.x * 4;
    float4 y4 = *(const float4*)(g_ysmall + row * DMODEL + d0);
    float y[4] = { y4.x, y4.y, y4.z, y4.w };
    float o[4];
    gn4(y, d0, gw, gb, o);
    *(float4*)(g_z + row * DMODEL + d0) = make_float4(o[0], o[1], o[2], o[3]);
}

// ================= launch =================
extern "C" void kernel_launch(void* const* d_in, const int* in_sizes, int n_in,
                              void* d_out, int out_size)
{
    const float* q   = (const float*)d_in[0];
    const float* k   = (const float*)d_in[1];
    const float* v   = (const float*)d_in[2];
    const float* wq  = (const float*)d_in[3];
    const float* wk  = (const float*)d_in[4];
    const float* wv  = (const float*)d_in[5];
    const float* wo  = (const float*)d_in[6];
    const float* wg  = (const float*)d_in[7];
    const float* wxw = (const float*)d_in[8];
    const float* wxb = (const float*)d_in[9];
    const float* gnw = (const float*)d_in[10];
    const float* gnb = (const float*)d_in[11];
    float* out = (float*)d_out;

    float *p_kpp, *p_tp;
    cudaGetSymbolAddress((void**)&p_kpp, g_kp_part);
    cudaGetSymbolAddress((void**)&p_tp,  g_T_part);

    __half *p_qhi, *p_khi, *p_klo, *p_ahi, *p_alo;
    __half *p_wkhi, *p_wghi, *p_wohi, *p_wxhi, *p_wxlo;
    __half *p_kxThi, *p_kxTlo, *p_vThi, *p_vTlo;
    cudaGetSymbolAddress((void**)&p_qhi,  g_qhi);
    cudaGetSymbolAddress((void**)&p_khi,  g_khi);  cudaGetSymbolAddress((void**)&p_klo,  g_klo);
    cudaGetSymbolAddress((void**)&p_ahi,  g_ahi);  cudaGetSymbolAddress((void**)&p_alo,  g_alo);
    cudaGetSymbolAddress((void**)&p_wkhi, g_wkhi);
    cudaGetSymbolAddress((void**)&p_wghi, g_wghi);
    cudaGetSymbolAddress((void**)&p_wohi, g_wohi);
    cudaGetSymbolAddress((void**)&p_wxhi, g_wxhi); cudaGetSymbolAddress((void**)&p_wxlo, g_wxlo);
    cudaGetSymbolAddress((void**)&p_kxThi, g_kxThi); cudaGetSymbolAddress((void**)&p_kxTlo, g_kxTlo);
    cudaGetSymbolAddress((void**)&p_vThi,  g_vThi);  cudaGetSymbolAddress((void**)&p_vTlo,  g_vTlo);

    cudaFuncSetAttribute((const void*)hmma_gemm<0, 2>, cudaFuncAttributeMaxDynamicSharedMemorySize, SMEM_MAIN);
    cudaFuncSetAttribute((const void*)hmma_gemm<1, 2>, cudaFuncAttributeMaxDynamicSharedMemorySize, SMEM_MAIN);
    cudaFuncSetAttribute((const void*)hmma_gemm<2, 1>, cudaFuncAttributeMaxDynamicSharedMemorySize, SMEM_MAIN);
    cudaFuncSetAttribute((const void*)seq_hmma, cudaFuncAttributeMaxDynamicSharedMemorySize, SMEM_SEQ);

    build_tables<<<(SEQ * HALF + 255) / 256, 256>>>();

    const int nact4 = MTOT * DMODEL / 4;
    const int nw4   = DMODEL * DMODEL / 4;
    const int nwx4  = DKC * SEQ / 4;
    split_half<<<nact4 / 256, 256>>>(k,   p_khi, p_klo, nact4);   // k hi/lo (wk 2-pass)
    split_hi  <<<nact4 / 256, 256>>>(q,   p_qhi, nact4);          // q hi only (wg 1-pass)
    split_hi  <<<nw4 / 256, 256>>>(wk,  p_wkhi, nw4);
    split_hi  <<<nw4 / 256, 256>>>(wg,  p_wghi, nw4);
    split_hi  <<<nw4 / 256, 256>>>(wo,  p_wohi, nw4);
    split_half<<<nwx4 / 256, 256>>>(wxw, p_wxhi, p_wxlo, nwx4);

    vt_split<<<dim3(SEQ / 64, DMODEL / 64, BATCH), 256>>>(v, p_vThi, p_vTlo);

    // keyxT = xpos(k @ wk^T)^T fp16 hi/lo, 2-pass HMMA
    hmma_gemm<1, 2><<<dim3(8, 128), 512, SMEM_MAIN>>>(p_khi, p_klo, p_wkhi,
                                                      nullptr, p_kxThi, p_kxTlo);
    // qs = xpos(q @ wq^T) rows s<64 (fp32)
    qs_gemm<<<dim3(16, BATCH, NSEG), 256>>>(q, wq);
    finish_qs<<<(BATCH * DKC * HALF) / 256, 256>>>();

    // kp / T seq contractions via fp16 HMMA (3-term, exact-ish)
    seq_hmma<<<dim3(8, BATCH, NSEG), 256, SMEM_SEQ>>>(p_kxThi, p_kxTlo, p_kpp);
    seq_hmma<<<dim3(8, BATCH, NSEG), 256, SMEM_SEQ>>>(p_vThi,  p_vTlo,  p_tp);
    finish_kp<<<(BATCH * DKC * DMODEL) / 256, 256>>>(wxb);
    finish_T <<<(BATCH * DKC * DMODEL) / 256, 256>>>();

    vp_kernel<<<dim3(16, BATCH), 256>>>(wv, wxb);
    attn_small<<<dim3(HEADS, BATCH), 64>>>();
    zbar_kernel<<<BATCH, 256>>>(gnw, gnb);
    gn_small<<<BATCH * DKC, 256>>>(gnw, gnb);

    // act = silu((q @ wg^T) * z) -> fp16 hi/lo, 1-pass HMMA
    hmma_gemm<2, 1><<<dim3(8, 128), 512, SMEM_MAIN>>>(p_qhi, nullptr, p_wghi,
                                                      nullptr, p_ahi, p_alo);
    // out = act @ wo^T, 2-pass HMMA
    hmma_gemm<0, 2><<<dim3(8, 128), 512, SMEM_MAIN>>>(p_ahi, p_alo, p_wohi,
                                                      out, nullptr, nullptr);
}

// round 11
// speedup vs baseline: 2.7677x; 1.2788x over previous
#include <cuda_runtime.h>
#include <cuda_fp16.h>
#include <math.h>
#include <stdint.h>

#define BATCH   4
#define SEQ     4096
#define DMODEL  1024
#define HEADS   16
#define DKC     64
#define HALF    512
#define NSEG    4
#define MTOT    (BATCH * SEQ)    /* 16384 */

// ---------------- scratch (device globals; no allocations) ----------------
__device__ float g_cos[SEQ * HALF];
__device__ float g_sin[SEQ * HALF];
__device__ float g_qs[BATCH * DKC * DMODEL];
__device__ float g_qs_part[NSEG * BATCH * DKC * DMODEL];
__device__ float g_kp_part[NSEG * BATCH * DKC * DMODEL];
__device__ float g_T_part [NSEG * BATCH * DKC * DMODEL];
__device__ float g_kp[BATCH * DKC * DMODEL];            // kp[b][e][d]
__device__ float g_T [BATCH * DKC * DMODEL];            // T[b][e][c]
__device__ float g_vp[BATCH * DMODEL * DKC];            // vp[b][f][e]
__device__ float g_ysmall[BATCH * DKC * DMODEL];
__device__ float g_z[BATCH * DKC * DMODEL];
__device__ float g_zbar[BATCH * DMODEL];

// fp16 operands
__device__ __half g_qhi[MTOT * DMODEL];                 // q hi (wg 1-pass)
__device__ __half g_khi[MTOT * DMODEL];                 // k hi (wk 1-pass)
__device__ __half g_ahi[MTOT * DMODEL];                 // silu(gate) hi (wo 1-pass)
__device__ __half g_wkhi[DMODEL * DMODEL];
__device__ __half g_wghi[DMODEL * DMODEL];
__device__ __half g_wohi[DMODEL * DMODEL];
__device__ __half g_wxhi[DKC * SEQ], g_wxlo[DKC * SEQ];
// transposed seq-major operands [b*DMODEL + d][SEQ]
__device__ __half g_kxThi[BATCH * DMODEL * SEQ];
__device__ __half g_vThi [BATCH * DMODEL * SEQ], g_vTlo [BATCH * DMODEL * SEQ];

// ================= PTX helpers =================
__device__ __forceinline__ uint32_t smem_u32(const void* p) {
    uint32_t a;
    asm("{ .reg .u64 t; cvta.to.shared.u64 t, %1; cvt.u32.u64 %0, t; }" : "=r"(a) : "l"(p));
    return a;
}
__device__ __forceinline__ void cp16(uint32_t dst, const void* src) {
    asm volatile("cp.async.cg.shared.global [%0], [%1], 16;" :: "r"(dst), "l"(src) : "memory");
}
#define CP_COMMIT() asm volatile("cp.async.commit_group;" ::: "memory")
#define CP_WAIT(N)  asm volatile("cp.async.wait_group %0;" :: "n"(N) : "memory")

__device__ __forceinline__ void ldsm4(uint32_t* r, uint32_t addr) {
    asm volatile("ldmatrix.sync.aligned.m8n8.x4.shared.b16 {%0,%1,%2,%3}, [%4];"
                 : "=r"(r[0]), "=r"(r[1]), "=r"(r[2]), "=r"(r[3]) : "r"(addr));
}
__device__ __forceinline__ void mma16816(float* d, const uint32_t* a, const uint32_t* b) {
    asm volatile("mma.sync.aligned.m16n8k16.row.col.f32.f16.f16.f32 "
                 "{%0,%1,%2,%3}, {%4,%5,%6,%7}, {%8,%9}, {%0,%1,%2,%3};"
                 : "+f"(d[0]), "+f"(d[1]), "+f"(d[2]), "+f"(d[3])
                 : "r"(a[0]), "r"(a[1]), "r"(a[2]), "r"(a[3]), "r"(b[0]), "r"(b[1]));
}

// SMEM: rows padded to 80B; tiles: 0=Ahi 1=Alo 2=Whi ; 3 stages
#define ROWB      80
#define TILE_B    10240
#define STG_BYTES 40960
#define SMEM_MAIN (3 * STG_BYTES)   /* 122880 */
#define TP_PAD    136

// seq GEMM SMEM
#define SQ_STG    30720
#define SQ_ALO    5120
#define SQ_B      10240
#define SQ_BLO    10240
#define SMEM_SEQ  (3 * SQ_STG)

// ================= xpos tables =================
__global__ void build_tables() {
    int idx = blockIdx.x * blockDim.x + threadIdx.x;
    if (idx >= SEQ * HALF) return;
    int s = idx / HALF, i = idx % HALF;
    float sv    = (2.0f * i + 0.4f * DMODEL) / (1.4f * DMODEL);
    float scale = powf(sv, (float)s / 512.0f);
    float invf  = powf(10000.0f, -(float)i / (float)HALF);
    float ang   = (float)s * invf;
    g_cos[idx] = cosf(ang) * scale;
    g_sin[idx] = sinf(ang) * scale;
}

// ================= fp32 -> fp16 conversions =================
__global__ void split_half(const float* __restrict__ x, __half* __restrict__ hi,
                           __half* __restrict__ lo, int n4) {
    int i = blockIdx.x * blockDim.x + threadIdx.x;
    if (i >= n4) return;
    float4 v = ((const float4*)x)[i];
    __half h0 = __float2half(v.x), h1 = __float2half(v.y);
    __half h2 = __float2half(v.z), h3 = __float2half(v.w);
    __half l0 = __float2half(v.x - __half2float(h0));
    __half l1 = __float2half(v.y - __half2float(h1));
    __half l2 = __float2half(v.z - __half2float(h2));
    __half l3 = __float2half(v.w - __half2float(h3));
    __half2* ph = (__half2*)(hi) + i * 2;
    __half2* pl = (__half2*)(lo) + i * 2;
    ph[0] = __half2(h0, h1); ph[1] = __half2(h2, h3);
    pl[0] = __half2(l0, l1); pl[1] = __half2(l2, l3);
}
__global__ void split_hi(const float* __restrict__ x, __half* __restrict__ hi, int n4) {
    int i = blockIdx.x * blockDim.x + threadIdx.x;
    if (i >= n4) return;
    float4 v = ((const float4*)x)[i];
    __half2* ph = (__half2*)(hi) + i * 2;
    ph[0] = __half2(__float2half(v.x), __float2half(v.y));
    ph[1] = __half2(__float2half(v.z), __float2half(v.w));
}

// ================= v -> vT hi/lo (transpose + split) =================
__global__ __launch_bounds__(256)
void vt_split(const float* __restrict__ v, __half* __restrict__ th,
              __half* __restrict__ tl)
{
    __shared__ float ts[64][65];
    const int s0 = blockIdx.x * 64, c0 = blockIdx.y * 64, b = blockIdx.z;
    const int tid = threadIdx.x;
    const int r = tid >> 2, quad = tid & 3;
#pragma unroll
    for (int j = 0; j < 4; ++j) {
        int col = quad * 16 + j * 4;
        float4 x = *(const float4*)(v + ((size_t)b * SEQ + s0 + r) * DMODEL + c0 + col);
        ts[r][col] = x.x; ts[r][col + 1] = x.y; ts[r][col + 2] = x.z; ts[r][col + 3] = x.w;
    }
    __syncthreads();
    uint4 hv[2], lv[2];
    __half* hh = (__half*)hv;
    __half* ll = (__half*)lv;
#pragma unroll
    for (int j = 0; j < 16; ++j) {
        float x = ts[quad * 16 + j][r];
        hh[j] = __float2half(x);
        ll[j] = __float2half(x - __half2float(hh[j]));
    }
    size_t row = ((size_t)b * DMODEL + c0 + r) * SEQ + s0 + quad * 16;
    *(uint4*)(th + row) = hv[0]; *(uint4*)(th + row + 8) = hv[1];
    *(uint4*)(tl + row) = lv[0]; *(uint4*)(tl + row + 8) = lv[1];
}

// ================= HMMA GEMM: C[m,n] = sum_k A[m,k]*W[n,k] =================
// CTA 128x128, 16 warps (4x4), warp tile 32x32, K chunks of 32, 3-stage ring.
// PASSES=2: AhWh + AlWh ; PASSES=1: AhWh only.
// EPI: 0 fp32 out ; 1 xpos -> keyxT fp16 hi transposed ; 2 gate*z+silu -> fp16 hi (+lo opt).
template<int PASSES>
__device__ __forceinline__ void load_stage512(
    uint32_t sb, int slot, int kc, int m0, int n0, int tid,
    const __half* __restrict__ Ahi, const __half* __restrict__ Alo,
    const __half* __restrict__ Whi)
{
    const uint32_t base = sb + (uint32_t)slot * STG_BYTES;
    const int koff = kc * 32;
    const int NT = PASSES + 1;
#pragma unroll
    for (int it = 0; it < NT; ++it) {
        int i = it * 512 + tid;
        int t = i >> 9;
        int tile = (PASSES == 1) ? (t * 2) : t;   // P=1: tiles {0,2}
        int r = (i >> 2) & 127, u = i & 3;
        const __half* src;
        if      (tile == 0) src = Ahi + (size_t)(m0 + r) * DMODEL + koff + u * 8;
        else if (tile == 1) src = Alo + (size_t)(m0 + r) * DMODEL + koff + u * 8;
        else                src = Whi + (size_t)(n0 + r) * DMODEL + koff + u * 8;
        cp16(base + (uint32_t)(tile * TILE_B + r * ROWB + u * 16), src);
    }
    CP_COMMIT();
}

template<int EPI, int PASSES>
__global__ __launch_bounds__(512)
void hmma_gemm(const __half* __restrict__ Ahi, const __half* __restrict__ Alo,
               const __half* __restrict__ Whi,
               float* __restrict__ Cf,
               __half* __restrict__ Chi, __half* __restrict__ Clo)
{
    extern __shared__ char smem[];
    const uint32_t sb = smem_u32(smem);
    const int tid = threadIdx.x, wid = tid >> 5, lane = tid & 31;
    const int warp_m = wid >> 2, warp_n = wid & 3;
    const int n0 = blockIdx.x * 128, m0 = blockIdx.y * 128;

    float acc[2][4][4];
#pragma unroll
    for (int i = 0; i < 2; ++i)
#pragma unroll
        for (int j = 0; j < 4; ++j)
#pragma unroll
            for (int c = 0; c < 4; ++c) acc[i][j][c] = 0.f;

    uint32_t aoff[2], boff[2];
#pragma unroll
    for (int a = 0; a < 2; ++a)
        aoff[a] = (uint32_t)((warp_m * 32 + a * 16 + (lane & 15)) * ROWB
                             + ((lane >> 4) & 1) * 16);
#pragma unroll
    for (int p = 0; p < 2; ++p)
        boff[p] = (uint32_t)((warp_n * 32 + p * 16 + (lane & 7) + ((lane >> 4) << 3)) * ROWB
                             + ((lane >> 3) & 1) * 16);

    load_stage512<PASSES>(sb, 0, 0, m0, n0, tid, Ahi, Alo, Whi);
    load_stage512<PASSES>(sb, 1, 1, m0, n0, tid, Ahi, Alo, Whi);

    for (int kc = 0; kc < 32; ++kc) {
        if (kc >= 30) { CP_WAIT(0); } else { CP_WAIT(1); }
        __syncthreads();
        if (kc + 2 < 32)
            load_stage512<PASSES>(sb, (kc + 2) % 3, kc + 2, m0, n0, tid, Ahi, Alo, Whi);
        const uint32_t stgb = sb + (uint32_t)(kc % 3) * STG_BYTES;
#pragma unroll
        for (int ks = 0; ks < 2; ++ks) {
            const uint32_t kb = (uint32_t)(ks * 32);
            uint32_t ahi[2][4], alo[2][4], bhi[2][4];
#pragma unroll
            for (int a = 0; a < 2; ++a) {
                ldsm4(ahi[a], stgb + aoff[a] + kb);
                if (PASSES >= 2) ldsm4(alo[a], stgb + TILE_B + aoff[a] + kb);
            }
#pragma unroll
            for (int p = 0; p < 2; ++p)
                ldsm4(bhi[p], stgb + 2 * TILE_B + boff[p] + kb);
#pragma unroll
            for (int im = 0; im < 2; ++im)
#pragma unroll
                for (int in = 0; in < 4; ++in)
                    mma16816(acc[im][in], ahi[im], &bhi[in >> 1][(in & 1) * 2]);
            if (PASSES >= 2) {
#pragma unroll
                for (int im = 0; im < 2; ++im)
#pragma unroll
                    for (int in = 0; in < 4; ++in)
                        mma16816(acc[im][in], alo[im], &bhi[in >> 1][(in & 1) * 2]);
            }
        }
    }

    // -------- epilogue --------
    if (EPI == 1) {
        __syncthreads();   // stage slots reused as transpose buffer
        __half* sh = (__half*)smem;
#pragma unroll
        for (int im = 0; im < 2; ++im)
#pragma unroll
            for (int in = 0; in < 4; ++in) {
                const int dl = warp_n * 32 + in * 8 + (lane & 3) * 2;
                const int nc = n0 + dl;
#pragma unroll
                for (int half = 0; half < 2; ++half) {
                    const int ml = warp_m * 32 + im * 16 + (lane >> 2) + half * 8;
                    const int s = (m0 + ml) & (SEQ - 1);
                    float v0 = acc[im][in][half * 2 + 0];
                    float v1 = acc[im][in][half * 2 + 1];
                    int p = s * HALF + (nc >> 1);
                    float cs = g_cos[p], sn = g_sin[p];
                    float o0 = v0 * cs - v1 * sn;
                    float o1 = v1 * cs + v0 * sn;
                    sh[dl * TP_PAD + ml] = __float2half(o0);
                    sh[(dl + 1) * TP_PAD + ml] = __float2half(o1);
                }
            }
        __syncthreads();
        const int s0 = m0 & (SEQ - 1), bb = m0 >> 12;
#pragma unroll
        for (int it = 0; it < 4; ++it) {
            int slot = it * 512 + tid;
            int dr = slot >> 4;
            int sc = (slot & 15) * 8;
            size_t grow = ((size_t)(bb * DMODEL + n0 + dr)) * SEQ + s0 + sc;
            *(uint4*)(Chi + grow) = *(uint4*)(sh + dr * TP_PAD + sc);
        }
        return;
    }
#pragma unroll
    for (int im = 0; im < 2; ++im) {
#pragma unroll
        for (int in = 0; in < 4; ++in) {
            const int nc = n0 + warp_n * 32 + in * 8 + (lane & 3) * 2;
#pragma unroll
            for (int half = 0; half < 2; ++half) {
                const int m = m0 + warp_m * 32 + im * 16 + (lane >> 2) + half * 8;
                const int s = m & (SEQ - 1);
                const int bb = m >> 12;
                float v0 = acc[im][in][half * 2 + 0];
                float v1 = acc[im][in][half * 2 + 1];
                if (EPI == 0) {
                    *(float2*)(Cf + (size_t)m * DMODEL + nc) = make_float2(v0, v1);
                } else {
                    const float* zr = (s < DKC) ? (g_z + (bb * DKC + s) * DMODEL)
                                                : (g_zbar + bb * DMODEL);
                    float a0 = v0 * zr[nc];
                    float a1 = v1 * zr[nc + 1];
                    a0 = a0 / (1.f + expf(-a0));
                    a1 = a1 / (1.f + expf(-a1));
                    __half h0 = __float2half(a0), h1 = __float2half(a1);
                    *(__half2*)(Chi + (size_t)m * DMODEL + nc) = __half2(h0, h1);
                    if (Clo) {
                        __half l0 = __float2half(a0 - __half2float(h0));
                        __half l1 = __float2half(a1 - __half2float(h1));
                        *(__half2*)(Clo + (size_t)m * DMODEL + nc) = __half2(l0, l1);
                    }
                }
            }
        }
    }
}

// ================= seq HMMA GEMM: C[e,n] = sum_s wx[e,s] * B[n,s] =================
// PASSES=3: AhBh + AlBh + AhBl ; PASSES=1: AhBh only.
template<int PASSES>
__device__ __forceinline__ void seq_load_stage(
    uint32_t sb, int stage, int k0, int brow0, int tid,
    const __half* __restrict__ Ah, const __half* __restrict__ Al,
    const __half* __restrict__ Bh, const __half* __restrict__ Bl)
{
    const uint32_t base = sb + (uint32_t)stage * SQ_STG;
    const int NA = (PASSES == 3) ? 2 : 1;
#pragma unroll
    for (int it = 0; it < NA; ++it) {
        int i = it * 256 + tid;
        int hl = i >> 8, r = (i >> 2) & 63, u = i & 3;
        const __half* src = (hl ? Al : Ah) + (size_t)r * SEQ + k0 + u * 8;
        cp16(base + (uint32_t)(hl * SQ_ALO + r * ROWB + u * 16), src);
    }
    const int NB = (PASSES == 3) ? 4 : 2;
#pragma unroll
    for (int it = 0; it < NB; ++it) {
        int i = it * 256 + tid;
        int hl = i >> 9, r = (i >> 2) & 127, u = i & 3;
        const __half* src = (hl ? Bl : Bh) + (size_t)(brow0 + r) * SEQ + k0 + u * 8;
        cp16(base + (uint32_t)(SQ_B + hl * SQ_BLO + r * ROWB + u * 16), src);
    }
    CP_COMMIT();
}

template<int PASSES>
__global__ __launch_bounds__(256)
void seq_hmma(const __half* __restrict__ Bh, const __half* __restrict__ Bl,
              float* __restrict__ part)
{
    extern __shared__ char smem[];
    const uint32_t sb = smem_u32(smem);
    const int tid = threadIdx.x, wid = tid >> 5, lane = tid & 31;
    const int n0 = blockIdx.x * 128, b = blockIdx.y, seg = blockIdx.z;
    const int brow0 = b * DMODEL + n0;
    const int kbase = seg * 1024;

    float acc[4][2][4];
#pragma unroll
    for (int i = 0; i < 4; ++i)
#pragma unroll
        for (int j = 0; j < 2; ++j)
#pragma unroll
            for (int c = 0; c < 4; ++c) acc[i][j][c] = 0.f;

    uint32_t aoff[4];
#pragma unroll
    for (int atom = 0; atom < 4; ++atom)
        aoff[atom] = (uint32_t)((atom * 16 + (lane & 15)) * ROWB + ((lane >> 4) & 1) * 16);
    const uint32_t boff = (uint32_t)((wid * 16 + (lane & 7) + ((lane >> 4) << 3)) * ROWB
                                     + ((lane >> 3) & 1) * 16);

    const __half* Ah = g_wxhi;
    const __half* Al = g_wxlo;
    seq_load_stage<PASSES>(sb, 0, kbase + 0,  brow0, tid, Ah, Al, Bh, Bl);
    seq_load_stage<PASSES>(sb, 1, kbase + 32, brow0, tid, Ah, Al, Bh, Bl);

    for (int kc = 0; kc < 32; ++kc) {
        if (kc >= 30) { CP_WAIT(0); } else { CP_WAIT(1); }
        __syncthreads();
        if (kc + 2 < 32)
            seq_load_stage<PASSES>(sb, (kc + 2) % 3, kbase + (kc + 2) * 32, brow0, tid, Ah, Al, Bh, Bl);
        const uint32_t stgb = sb + (uint32_t)(kc % 3) * SQ_STG;
#pragma unroll
        for (int ks = 0; ks < 2; ++ks) {
            const uint32_t kb = (uint32_t)(ks * 32);
            uint32_t ahi[4][4], alo[4][4], bhi[4], blo[4];
#pragma unroll
            for (int atom = 0; atom < 4; ++atom) {
                ldsm4(ahi[atom], stgb + aoff[atom] + kb);
                if (PASSES == 3) ldsm4(alo[atom], stgb + SQ_ALO + aoff[atom] + kb);
            }
            ldsm4(bhi, stgb + SQ_B + boff + kb);
            if (PASSES == 3) ldsm4(blo, stgb + SQ_B + SQ_BLO + boff + kb);
#pragma unroll
            for (int im = 0; im < 4; ++im)
#pragma unroll
                for (int in = 0; in < 2; ++in)
                    mma16816(acc[im][in], ahi[im], &bhi[in * 2]);
            if (PASSES == 3) {
#pragma unroll
                for (int im = 0; im < 4; ++im)
#pragma unroll
                    for (int in = 0; in < 2; ++in)
                        mma16816(acc[im][in], alo[im], &bhi[in * 2]);
#pragma unroll
                for (int im = 0; im < 4; ++im)
#pragma unroll
                    for (int in = 0; in < 2; ++in)
                        mma16816(acc[im][in], ahi[im], &blo[in * 2]);
            }
        }
    }

    const size_t obase = (size_t)seg * (BATCH * DKC * DMODEL);
#pragma unroll
    for (int im = 0; im < 4; ++im)
#pragma unroll
        for (int in = 0; in < 2; ++in) {
            const int n = n0 + wid * 16 + in * 8 + (lane & 3) * 2;
#pragma unroll
            for (int half = 0; half < 2; ++half) {
                const int e = im * 16 + (lane >> 2) + half * 8;
                *(float2*)(part + obase + ((size_t)(b * DKC + e) << 10) + n) =
                    make_float2(acc[im][in][half * 2], acc[im][in][half * 2 + 1]);
            }
        }
}

__global__ void finish_kp(const float* __restrict__ wxb) {
    int idx = blockIdx.x * blockDim.x + threadIdx.x;
    float v = 0.f;
#pragma unroll
    for (int s = 0; s < NSEG; ++s) v += g_kp_part[s * (BATCH * DKC * DMODEL) + idx];
    g_kp[idx] = v + wxb[(idx >> 10) & 63];
}
__global__ void finish_T() {
    int idx = blockIdx.x * blockDim.x + threadIdx.x;
    float v = 0.f;
#pragma unroll
    for (int s = 0; s < NSEG; ++s) v += g_T_part[s * (BATCH * DKC * DMODEL) + idx];
    g_T[idx] = v;
}

// ================= qs: split-K SIMT GEMM (rows s<64 only) =================
__global__ __launch_bounds__(256)
void qs_gemm(const float* __restrict__ q, const float* __restrict__ wq)
{
    __shared__ float As[16][68];
    __shared__ float Bs[16][68];
    const int n0 = blockIdx.x * 64, b = blockIdx.y, seg = blockIdx.z;
    const int tid = threadIdx.x;
    const int ti = tid & 15, te = tid >> 4;
    const int lr = tid >> 2, lc = (tid & 3) * 4;

    float acc[4][4];
#pragma unroll
    for (int i = 0; i < 4; ++i)
#pragma unroll
        for (int j = 0; j < 4; ++j) acc[i][j] = 0.f;

    for (int kt = 0; kt < 16; ++kt) {
        const int k0 = seg * 256 + kt * 16;
        float4 pa = *(const float4*)(q  + ((size_t)b * SEQ + lr) * DMODEL + k0 + lc);
        float4 pb = *(const float4*)(wq + (size_t)(n0 + lr) * DMODEL + k0 + lc);
        As[lc + 0][lr] = pa.x; As[lc + 1][lr] = pa.y; As[lc + 2][lr] = pa.z; As[lc + 3][lr] = pa.w;
        Bs[lc + 0][lr] = pb.x; Bs[lc + 1][lr] = pb.y; Bs[lc + 2][lr] = pb.z; Bs[lc + 3][lr] = pb.w;
        __syncthreads();
#pragma unroll
        for (int kk = 0; kk < 16; ++kk) {
            float a[4], bb[4];
            *(float4*)a  = *(const float4*)&As[kk][te * 4];
            *(float4*)bb = *(const float4*)&Bs[kk][ti * 4];
#pragma unroll
            for (int i = 0; i < 4; ++i)
#pragma unroll
                for (int j = 0; j < 4; ++j)
                    acc[i][j] = fmaf(a[i], bb[j], acc[i][j]);
        }
        __syncthreads();
    }
    const size_t obase = (size_t)seg * (BATCH * DKC * DMODEL);
#pragma unroll
    for (int i = 0; i < 4; ++i)
#pragma unroll
        for (int j = 0; j < 4; ++j)
            g_qs_part[obase + ((size_t)(b * DKC + te * 4 + i) << 10) + n0 + ti * 4 + j] = acc[i][j];
}

__global__ void finish_qs() {
    int idx = blockIdx.x * blockDim.x + threadIdx.x;
    int m = idx >> 9, pr = idx & 511;
    float v0 = 0.f, v1 = 0.f;
#pragma unroll
    for (int s = 0; s < NSEG; ++s) {
        const float* p = g_qs_part + (size_t)s * (BATCH * DKC * DMODEL) + ((size_t)m << 10) + pr * 2;
        v0 += p[0]; v1 += p[1];
    }
    int sq = m & 63;
    int p = sq * HALF + pr;
    float cs = g_cos[p], sn = g_sin[p];
    g_qs[((size_t)m << 10) + pr * 2]     = v0 * cs - v1 * sn;
    g_qs[((size_t)m << 10) + pr * 2 + 1] = v1 * cs + v0 * sn;
}

// ================= vp[b,f,e] = sum_c wv[f,c]*T[b,e,c] + wxb[e] =================
__global__ __launch_bounds__(256)
void vp_kernel(const float* __restrict__ wv, const float* __restrict__ wxb)
{
    __shared__ float Wvs[64][68];
    __shared__ float Ts[64][68];
    const int f0 = blockIdx.x * 64;
    const int b  = blockIdx.y;
    const int tid = threadIdx.x;
    const int tf = tid & 15, te = tid >> 4;
    float acc[4][4];
#pragma unroll
    for (int a = 0; a < 4; ++a)
#pragma unroll
        for (int j = 0; j < 4; ++j) acc[a][j] = 0.f;

    for (int ch = 0; ch < 16; ++ch) {
        int cb = ch * 64;
#pragma unroll
        for (int r = 0; r < 16; ++r) {
            int l = r * 256 + tid;
            int row = l >> 6, col = l & 63;
            Wvs[row][col] = wv[(f0 + row) * DMODEL + cb + col];
            Ts[row][col]  = g_T[(b * DKC + row) * DMODEL + cb + col];
        }
        __syncthreads();
        for (int c = 0; c < 64; ++c) {
            float wf0 = Wvs[tf * 4 + 0][c], wf1 = Wvs[tf * 4 + 1][c];
            float wf2 = Wvs[tf * 4 + 2][c], wf3 = Wvs[tf * 4 + 3][c];
            float t0 = Ts[te * 4 + 0][c], t1 = Ts[te * 4 + 1][c];
            float t2 = Ts[te * 4 + 2][c], t3 = Ts[te * 4 + 3][c];
            acc[0][0] += wf0 * t0; acc[0][1] += wf0 * t1; acc[0][2] += wf0 * t2; acc[0][3] += wf0 * t3;
            acc[1][0] += wf1 * t0; acc[1][1] += wf1 * t1; acc[1][2] += wf1 * t2; acc[1][3] += wf1 * t3;
            acc[2][0] += wf2 * t0; acc[2][1] += wf2 * t1; acc[2][2] += wf2 * t2; acc[2][3] += wf2 * t3;
            acc[3][0] += wf3 * t0; acc[3][1] += wf3 * t1; acc[3][2] += wf3 * t2; acc[3][3] += wf3 * t3;
        }
        __syncthreads();
    }
#pragma unroll
    for (int a = 0; a < 4; ++a)
#pragma unroll
        for (int j = 0; j < 4; ++j) {
            int f = f0 + tf * 4 + a, e = te * 4 + j;
            g_vp[(b * DMODEL + f) * DKC + e] = acc[a][j] + wxb[e];
        }
}

// ================= tiny attention (s < 64 rows) =================
__global__ __launch_bounds__(64)
void attn_small()
{
    __shared__ float kps[64][64];
    __shared__ float vps[64][64];
    const int h = blockIdx.x, b = blockIdx.y, s = threadIdx.x;
#pragma unroll 4
    for (int e = 0; e < 64; ++e)
        kps[s][e] = g_kp[((size_t)(b * DKC + e) << 10) + h * DKC + s];
    for (int l = s; l < 4096; l += 64) {
        int d = l >> 6, e = l & 63;
        vps[d][e] = g_vp[(b * DMODEL + h * DKC + d) * DKC + e];
    }
    __syncthreads();

    float qv[64];
    const float* qp = g_qs + (b * DKC + s) * DMODEL + h * DKC;
#pragma unroll
    for (int d = 0; d < 64; d += 4) {
        float4 t = *(const float4*)(qp + d);
        qv[d] = t.x; qv[d + 1] = t.y; qv[d + 2] = t.z; qv[d + 3] = t.w;
    }
    const float lg0 = logf(1.0f / 32.0f);
    const float lg1 = logf(1.0f / 512.0f);
    const float gamma = 1.0f - expf(lg0 + (lg1 - lg0) * ((float)h / 15.0f));

    float sc[64];
#pragma unroll
    for (int e = 0; e < 64; ++e) {
        float a = 0.f;
#pragma unroll
        for (int d = 0; d < 64; ++d) a = fmaf(qv[d], kps[d][e], a);
        float dt = (e >= s) ? powf(gamma, (float)(e - s)) : 0.0f;
        sc[e] = a * dt;
    }
    float mx = -1e30f;
#pragma unroll
    for (int e = 0; e < 64; ++e) mx = fmaxf(mx, sc[e]);
    float sum = 0.f;
#pragma unroll
    for (int e = 0; e < 64; ++e) { sc[e] = expf(sc[e] - mx); sum += sc[e]; }
    float inv = 1.0f / sum;
#pragma unroll
    for (int f = 0; f < 64; ++f) {
        float a = 0.f;
#pragma unroll
        for (int e = 0; e < 64; ++e) a = fmaf(sc[e], vps[f][e], a);
        g_ysmall[(b * DKC + s) * DMODEL + h * DKC + f] = a * inv;
    }
}

// ================= group norm =================
__device__ __forceinline__ void gn4(float y[4], int d0,
                                    const float* gw, const float* gb, float out[4]) {
    float mu = (y[0] + y[1] + y[2] + y[3]) * 0.25f;
    float var = 0.f;
#pragma unroll
    for (int j = 0; j < 4; ++j) { float dd = y[j] - mu; var += dd * dd; }
    var *= 0.25f;
    float inv = rsqrtf(var + 1e-5f);
#pragma unroll
    for (int j = 0; j < 4; ++j) {
        int d = d0 + j;
        out[j] = (y[j] - mu) * inv * gw[d & 63] + gb[d & 63];
    }
}

__global__ void zbar_kernel(const float* __restrict__ gw, const float* __restrict__ gb) {
    int b = blockIdx.x, t = threadIdx.x;
    int d0 = t * 4;
    float y[4];
#pragma unroll
    for (int j = 0; j < 4; ++j) {
        const float* vp = g_vp + (b * DMODEL + d0 + j) * DKC;
        float s = 0.f;
#pragma unroll
        for (int e = 0; e < 64; ++e) s += vp[e];
        y[j] = s * (1.0f / 64.0f);
    }
    float o[4];
    gn4(y, d0, gw, gb, o);
#pragma unroll
    for (int j = 0; j < 4; ++j) g_zbar[b * DMODEL + d0 + j] = o[j];
}

__global__ void gn_small(const float* __restrict__ gw, const float* __restrict__ gb) {
    int row = blockIdx.x;
    int d0 = threadIdx.x * 4;
    float4 y4 = *(const float4*)(g_ysmall + row * DMODEL + d0);
    float y[4] = { y4.x, y4.y, y4.z, y4.w };
    float o[4];
    gn4(y, d0, gw, gb, o);
    *(float4*)(g_z + row * DMODEL + d0) = make_float4(o[0], o[1], o[2], o[3]);
}

// ================= launch =================
extern "C" void kernel_launch(void* const* d_in, const int* in_sizes, int n_in,
                              void* d_out, int out_size)
{
    const float* q   = (const float*)d_in[0];
    const float* k   = (const float*)d_in[1];
    const float* v   = (const float*)d_in[2];
    const float* wq  = (const float*)d_in[3];
    const float* wk  = (const float*)d_in[4];
    const float* wv  = (const float*)d_in[5];
    const float* wo  = (const float*)d_in[6];
    const float* wg  = (const float*)d_in[7];
    const float* wxw = (const float*)d_in[8];
    const float* wxb = (const float*)d_in[9];
    const float* gnw = (const float*)d_in[10];
    const float* gnb = (const float*)d_in[11];
    float* out = (float*)d_out;

    float *p_kpp, *p_tp;
    cudaGetSymbolAddress((void**)&p_kpp, g_kp_part);
    cudaGetSymbolAddress((void**)&p_tp,  g_T_part);

    __half *p_qhi, *p_khi, *p_ahi;
    __half *p_wkhi, *p_wghi, *p_wohi, *p_wxhi, *p_wxlo;
    __half *p_kxThi, *p_vThi, *p_vTlo;
    cudaGetSymbolAddress((void**)&p_qhi,  g_qhi);
    cudaGetSymbolAddress((void**)&p_khi,  g_khi);
    cudaGetSymbolAddress((void**)&p_ahi,  g_ahi);
    cudaGetSymbolAddress((void**)&p_wkhi, g_wkhi);
    cudaGetSymbolAddress((void**)&p_wghi, g_wghi);
    cudaGetSymbolAddress((void**)&p_wohi, g_wohi);
    cudaGetSymbolAddress((void**)&p_wxhi, g_wxhi); cudaGetSymbolAddress((void**)&p_wxlo, g_wxlo);
    cudaGetSymbolAddress((void**)&p_kxThi, g_kxThi);
    cudaGetSymbolAddress((void**)&p_vThi,  g_vThi);  cudaGetSymbolAddress((void**)&p_vTlo,  g_vTlo);

    cudaFuncSetAttribute((const void*)hmma_gemm<0, 1>, cudaFuncAttributeMaxDynamicSharedMemorySize, SMEM_MAIN);
    cudaFuncSetAttribute((const void*)hmma_gemm<1, 1>, cudaFuncAttributeMaxDynamicSharedMemorySize, SMEM_MAIN);
    cudaFuncSetAttribute((const void*)hmma_gemm<2, 1>, cudaFuncAttributeMaxDynamicSharedMemorySize, SMEM_MAIN);
    cudaFuncSetAttribute((const void*)seq_hmma<1>, cudaFuncAttributeMaxDynamicSharedMemorySize, SMEM_SEQ);
    cudaFuncSetAttribute((const void*)seq_hmma<3>, cudaFuncAttributeMaxDynamicSharedMemorySize, SMEM_SEQ);

    build_tables<<<(SEQ * HALF + 255) / 256, 256>>>();

    const int nact4 = MTOT * DMODEL / 4;
    const int nw4   = DMODEL * DMODEL / 4;
    const int nwx4  = DKC * SEQ / 4;
    split_hi  <<<nact4 / 256, 256>>>(k,   p_khi, nact4);
    split_hi  <<<nact4 / 256, 256>>>(q,   p_qhi, nact4);
    split_hi  <<<nw4 / 256, 256>>>(wk,  p_wkhi, nw4);
    split_hi  <<<nw4 / 256, 256>>>(wg,  p_wghi, nw4);
    split_hi  <<<nw4 / 256, 256>>>(wo,  p_wohi, nw4);
    split_half<<<nwx4 / 256, 256>>>(wxw, p_wxhi, p_wxlo, nwx4);

    vt_split<<<dim3(SEQ / 64, DMODEL / 64, BATCH), 256>>>(v, p_vThi, p_vTlo);

    // keyxT = xpos(k @ wk^T)^T fp16 hi, 1-pass HMMA (kp path only affects s<64 rows)
    hmma_gemm<1, 1><<<dim3(8, 128), 512, SMEM_MAIN>>>(p_khi, nullptr, p_wkhi,
                                                      nullptr, p_kxThi, nullptr);
    // qs = xpos(q @ wq^T) rows s<64 (fp32)
    qs_gemm<<<dim3(16, BATCH, NSEG), 256>>>(q, wq);
    finish_qs<<<(BATCH * DKC * HALF) / 256, 256>>>();

    // kp: 1-term (diluted path); T: 3-term (feeds all rows)
    seq_hmma<1><<<dim3(8, BATCH, NSEG), 256, SMEM_SEQ>>>(p_kxThi, nullptr, p_kpp);
    seq_hmma<3><<<dim3(8, BATCH, NSEG), 256, SMEM_SEQ>>>(p_vThi,  p_vTlo,  p_tp);
    finish_kp<<<(BATCH * DKC * DMODEL) / 256, 256>>>(wxb);
    finish_T <<<(BATCH * DKC * DMODEL) / 256, 256>>>();

    vp_kernel<<<dim3(16, BATCH), 256>>>(wv, wxb);
    attn_small<<<dim3(HEADS, BATCH), 64>>>();
    zbar_kernel<<<BATCH, 256>>>(gnw, gnb);
    gn_small<<<BATCH * DKC, 256>>>(gnw, gnb);

    // act = silu((q @ wg^T) * z) -> fp16 hi, 1-pass HMMA
    hmma_gemm<2, 1><<<dim3(8, 128), 512, SMEM_MAIN>>>(p_qhi, nullptr, p_wghi,
                                                      nullptr, p_ahi, nullptr);
    // out = act @ wo^T, 1-pass HMMA
    hmma_gemm<0, 1><<<dim3(8, 128), 512, SMEM_MAIN>>>(p_ahi, nullptr, p_wohi,
                                                      out, nullptr, nullptr);
}

// round 12
// speedup vs baseline: 2.8939x; 1.0456x over previous
#include <cuda_runtime.h>
#include <cuda_fp16.h>
#include <math.h>
#include <stdint.h>

#define BATCH   4
#define SEQ     4096
#define DMODEL  1024
#define HEADS   16
#define DKC     64
#define HALF    512
#define NSEG    4
#define MTOT    (BATCH * SEQ)    /* 16384 */

// ---------------- scratch (device globals; no allocations) ----------------
__device__ float g_cos[SEQ * HALF];
__device__ float g_sin[SEQ * HALF];
__device__ float g_qs[BATCH * DKC * DMODEL];
__device__ float g_qs_part[NSEG * BATCH * DKC * DMODEL];
__device__ float g_kp_part[NSEG * BATCH * DKC * DMODEL];
__device__ float g_T_part [NSEG * BATCH * DKC * DMODEL];
__device__ float g_kp[BATCH * DKC * DMODEL];            // kp[b][e][d]
__device__ float g_T [BATCH * DKC * DMODEL];            // T[b][e][c]
__device__ float g_vp[BATCH * DMODEL * DKC];            // vp[b][f][e]
__device__ float g_ysmall[BATCH * DKC * DMODEL];
__device__ float g_z[BATCH * DKC * DMODEL];
__device__ float g_zbar[BATCH * DMODEL];

// fp16 operands
__device__ __half g_qhi[MTOT * DMODEL];
__device__ __half g_khi[MTOT * DMODEL];
__device__ __half g_ahi[MTOT * DMODEL];
__device__ __half g_wkhi[DMODEL * DMODEL];
__device__ __half g_wghi[DMODEL * DMODEL];
__device__ __half g_wohi[DMODEL * DMODEL];
__device__ __half g_wxhi[DKC * SEQ];
// transposed seq-major operands [b*DMODEL + d][SEQ]
__device__ __half g_kxThi[BATCH * DMODEL * SEQ];
__device__ __half g_vThi [BATCH * DMODEL * SEQ];

// ================= PTX helpers =================
__device__ __forceinline__ uint32_t smem_u32(const void* p) {
    uint32_t a;
    asm("{ .reg .u64 t; cvta.to.shared.u64 t, %1; cvt.u32.u64 %0, t; }" : "=r"(a) : "l"(p));
    return a;
}
__device__ __forceinline__ void cp16(uint32_t dst, const void* src) {
    asm volatile("cp.async.cg.shared.global [%0], [%1], 16;" :: "r"(dst), "l"(src) : "memory");
}
#define CP_COMMIT() asm volatile("cp.async.commit_group;" ::: "memory")
#define CP_WAIT(N)  asm volatile("cp.async.wait_group %0;" :: "n"(N) : "memory")

__device__ __forceinline__ void ldsm4(uint32_t* r, uint32_t addr) {
    asm volatile("ldmatrix.sync.aligned.m8n8.x4.shared.b16 {%0,%1,%2,%3}, [%4];"
                 : "=r"(r[0]), "=r"(r[1]), "=r"(r[2]), "=r"(r[3]) : "r"(addr));
}
__device__ __forceinline__ void mma16816(float* d, const uint32_t* a, const uint32_t* b) {
    asm volatile("mma.sync.aligned.m16n8k16.row.col.f32.f16.f16.f32 "
                 "{%0,%1,%2,%3}, {%4,%5,%6,%7}, {%8,%9}, {%0,%1,%2,%3};"
                 : "+f"(d[0]), "+f"(d[1]), "+f"(d[2]), "+f"(d[3])
                 : "r"(a[0]), "r"(a[1]), "r"(a[2]), "r"(a[3]), "r"(b[0]), "r"(b[1]));
}

// main GEMM SMEM: rows padded to 80B; tiles: 0=Ahi 2=Whi ; 3 stages
#define ROWB      80
#define TILE_B    10240
#define STG_BYTES 40960
#define SMEM_MAIN (3 * STG_BYTES)   /* 122880 */
#define TP_PAD    136

// seq GEMM SMEM (1-term): A 64x32, B 128x32 per stage
#define SQ_STG    15360
#define SQ_B      5120
#define SMEM_SEQ  (3 * SQ_STG)      /* 46080 */

// ================= xpos tables =================
__global__ void build_tables() {
    int idx = blockIdx.x * blockDim.x + threadIdx.x;
    if (idx >= SEQ * HALF) return;
    int s = idx / HALF, i = idx % HALF;
    float sv    = (2.0f * i + 0.4f * DMODEL) / (1.4f * DMODEL);
    float scale = exp2f(((float)s * (1.0f / 512.0f)) * log2f(sv));
    float invf  = exp2f(-(float)i * (13.287712379549449f / 512.0f));
    float ang   = (float)s * invf;
    float sn, cs;
    sincosf(ang, &sn, &cs);
    g_cos[idx] = cs * scale;
    g_sin[idx] = sn * scale;
}

// ================= fp32 -> fp16 conversions (batched) =================
__device__ __forceinline__ void conv_hi_body(const float* __restrict__ x,
                                             __half* __restrict__ hi, int i) {
    float4 v = ((const float4*)x)[i];
    __half2* ph = (__half2*)(hi) + i * 2;
    ph[0] = __half2(__float2half(v.x), __float2half(v.y));
    ph[1] = __half2(__float2half(v.z), __float2half(v.w));
}
__global__ void conv_qk(const float* __restrict__ q, const float* __restrict__ k,
                        __half* __restrict__ qhi, __half* __restrict__ khi, int n4) {
    int i = blockIdx.x * blockDim.x + threadIdx.x;
    if (i >= n4) return;
    if (blockIdx.y == 0) conv_hi_body(q, qhi, i);
    else                 conv_hi_body(k, khi, i);
}
__global__ void conv_w(const float* __restrict__ wk, const float* __restrict__ wg,
                       const float* __restrict__ wo,
                       __half* __restrict__ wkhi, __half* __restrict__ wghi,
                       __half* __restrict__ wohi, int n4) {
    int i = blockIdx.x * blockDim.x + threadIdx.x;
    if (i >= n4) return;
    int z = blockIdx.y;
    if      (z == 0) conv_hi_body(wk, wkhi, i);
    else if (z == 1) conv_hi_body(wg, wghi, i);
    else             conv_hi_body(wo, wohi, i);
}
__global__ void split_hi(const float* __restrict__ x, __half* __restrict__ hi, int n4) {
    int i = blockIdx.x * blockDim.x + threadIdx.x;
    if (i >= n4) return;
    conv_hi_body(x, hi, i);
}

// ================= v -> vT hi (transpose) =================
__global__ __launch_bounds__(256)
void vt_split(const float* __restrict__ v, __half* __restrict__ th)
{
    __shared__ float ts[64][65];
    const int s0 = blockIdx.x * 64, c0 = blockIdx.y * 64, b = blockIdx.z;
    const int tid = threadIdx.x;
    const int r = tid >> 2, quad = tid & 3;
#pragma unroll
    for (int j = 0; j < 4; ++j) {
        int col = quad * 16 + j * 4;
        float4 x = *(const float4*)(v + ((size_t)b * SEQ + s0 + r) * DMODEL + c0 + col);
        ts[r][col] = x.x; ts[r][col + 1] = x.y; ts[r][col + 2] = x.z; ts[r][col + 3] = x.w;
    }
    __syncthreads();
    uint4 hv[2];
    __half* hh = (__half*)hv;
#pragma unroll
    for (int j = 0; j < 16; ++j)
        hh[j] = __float2half(ts[quad * 16 + j][r]);
    size_t row = ((size_t)b * DMODEL + c0 + r) * SEQ + s0 + quad * 16;
    *(uint4*)(th + row) = hv[0]; *(uint4*)(th + row + 8) = hv[1];
}

// ================= HMMA 1-pass GEMM: C[m,n] = sum_k A[m,k]*W[n,k] =================
// CTA 128x128, 16 warps (4x4), warp tile 32x32, K chunks of 32, 3-stage ring.
// EPI: 0 fp32 out ; 1 xpos -> keyxT fp16 transposed ; 2 gate*z+silu -> fp16.
__device__ __forceinline__ void load_stage512(
    uint32_t sb, int slot, int kc, int m0, int n0, int tid,
    const __half* __restrict__ Ahi, const __half* __restrict__ Whi)
{
    const uint32_t base = sb + (uint32_t)slot * STG_BYTES;
    const int koff = kc * 32;
#pragma unroll
    for (int it = 0; it < 2; ++it) {
        int i = it * 512 + tid;
        int t = i >> 9;
        int tile = t * 2;   // tiles {0, 2}
        int r = (i >> 2) & 127, u = i & 3;
        const __half* src = (tile == 0) ? (Ahi + (size_t)(m0 + r) * DMODEL + koff + u * 8)
                                        : (Whi + (size_t)(n0 + r) * DMODEL + koff + u * 8);
        cp16(base + (uint32_t)(tile * TILE_B + r * ROWB + u * 16), src);
    }
    CP_COMMIT();
}

template<int EPI>
__global__ __launch_bounds__(512)
void hmma_gemm(const __half* __restrict__ Ahi, const __half* __restrict__ Whi,
               float* __restrict__ Cf, __half* __restrict__ Chi)
{
    extern __shared__ char smem[];
    const uint32_t sb = smem_u32(smem);
    const int tid = threadIdx.x, wid = tid >> 5, lane = tid & 31;
    const int warp_m = wid >> 2, warp_n = wid & 3;
    const int n0 = blockIdx.x * 128, m0 = blockIdx.y * 128;

    float acc[2][4][4];
#pragma unroll
    for (int i = 0; i < 2; ++i)
#pragma unroll
        for (int j = 0; j < 4; ++j)
#pragma unroll
            for (int c = 0; c < 4; ++c) acc[i][j][c] = 0.f;

    uint32_t aoff[2], boff[2];
#pragma unroll
    for (int a = 0; a < 2; ++a)
        aoff[a] = (uint32_t)((warp_m * 32 + a * 16 + (lane & 15)) * ROWB
                             + ((lane >> 4) & 1) * 16);
#pragma unroll
    for (int p = 0; p < 2; ++p)
        boff[p] = (uint32_t)((warp_n * 32 + p * 16 + (lane & 7) + ((lane >> 4) << 3)) * ROWB
                             + ((lane >> 3) & 1) * 16);

    load_stage512(sb, 0, 0, m0, n0, tid, Ahi, Whi);
    load_stage512(sb, 1, 1, m0, n0, tid, Ahi, Whi);

    for (int kc = 0; kc < 32; ++kc) {
        if (kc >= 30) { CP_WAIT(0); } else { CP_WAIT(1); }
        __syncthreads();
        if (kc + 2 < 32)
            load_stage512(sb, (kc + 2) % 3, kc + 2, m0, n0, tid, Ahi, Whi);
        const uint32_t stgb = sb + (uint32_t)(kc % 3) * STG_BYTES;
#pragma unroll
        for (int ks = 0; ks < 2; ++ks) {
            const uint32_t kb = (uint32_t)(ks * 32);
            uint32_t ahi[2][4], bhi[2][4];
#pragma unroll
            for (int a = 0; a < 2; ++a)
                ldsm4(ahi[a], stgb + aoff[a] + kb);
#pragma unroll
            for (int p = 0; p < 2; ++p)
                ldsm4(bhi[p], stgb + 2 * TILE_B + boff[p] + kb);
#pragma unroll
            for (int im = 0; im < 2; ++im)
#pragma unroll
                for (int in = 0; in < 4; ++in)
                    mma16816(acc[im][in], ahi[im], &bhi[in >> 1][(in & 1) * 2]);
        }
    }

    // -------- epilogue --------
    if (EPI == 1) {
        __syncthreads();   // stage slots reused as transpose buffer
        __half* sh = (__half*)smem;
#pragma unroll
        for (int im = 0; im < 2; ++im)
#pragma unroll
            for (int in = 0; in < 4; ++in) {
                const int dl = warp_n * 32 + in * 8 + (lane & 3) * 2;
                const int nc = n0 + dl;
#pragma unroll
                for (int half = 0; half < 2; ++half) {
                    const int ml = warp_m * 32 + im * 16 + (lane >> 2) + half * 8;
                    const int s = (m0 + ml) & (SEQ - 1);
                    float v0 = acc[im][in][half * 2 + 0];
                    float v1 = acc[im][in][half * 2 + 1];
                    int p = s * HALF + (nc >> 1);
                    float cs = g_cos[p], sn = g_sin[p];
                    float o0 = v0 * cs - v1 * sn;
                    float o1 = v1 * cs + v0 * sn;
                    sh[dl * TP_PAD + ml] = __float2half(o0);
                    sh[(dl + 1) * TP_PAD + ml] = __float2half(o1);
                }
            }
        __syncthreads();
        const int s0 = m0 & (SEQ - 1), bb = m0 >> 12;
#pragma unroll
        for (int it = 0; it < 4; ++it) {
            int slot = it * 512 + tid;
            int dr = slot >> 4;
            int sc = (slot & 15) * 8;
            size_t grow = ((size_t)(bb * DMODEL + n0 + dr)) * SEQ + s0 + sc;
            *(uint4*)(Chi + grow) = *(uint4*)(sh + dr * TP_PAD + sc);
        }
        return;
    }
#pragma unroll
    for (int im = 0; im < 2; ++im) {
#pragma unroll
        for (int in = 0; in < 4; ++in) {
            const int nc = n0 + warp_n * 32 + in * 8 + (lane & 3) * 2;
#pragma unroll
            for (int half = 0; half < 2; ++half) {
                const int m = m0 + warp_m * 32 + im * 16 + (lane >> 2) + half * 8;
                const int s = m & (SEQ - 1);
                const int bb = m >> 12;
                float v0 = acc[im][in][half * 2 + 0];
                float v1 = acc[im][in][half * 2 + 1];
                if (EPI == 0) {
                    *(float2*)(Cf + (size_t)m * DMODEL + nc) = make_float2(v0, v1);
                } else {
                    const float* zr = (s < DKC) ? (g_z + (bb * DKC + s) * DMODEL)
                                                : (g_zbar + bb * DMODEL);
                    float a0 = v0 * zr[nc];
                    float a1 = v1 * zr[nc + 1];
                    a0 = a0 / (1.f + expf(-a0));
                    a1 = a1 / (1.f + expf(-a1));
                    *(__half2*)(Chi + (size_t)m * DMODEL + nc) =
                        __half2(__float2half(a0), __float2half(a1));
                }
            }
        }
    }
}

// ================= merged seq HMMA (1-term): kp & T in one launch =================
// C[e,n] = sum_s wx[e,s] * B[n,s] ; grid (8, BATCH, 8): z>>2 selects kp vs T.
__device__ __forceinline__ void seq_load_stage1(
    uint32_t sb, int stage, int k0, int brow0, int tid,
    const __half* __restrict__ Ah, const __half* __restrict__ Bh)
{
    const uint32_t base = sb + (uint32_t)stage * SQ_STG;
    {
        int i = tid;
        int r = (i >> 2) & 63, u = i & 3;
        cp16(base + (uint32_t)(r * ROWB + u * 16), Ah + (size_t)r * SEQ + k0 + u * 8);
    }
#pragma unroll
    for (int it = 0; it < 2; ++it) {
        int i = it * 256 + tid;
        int r = (i >> 2) & 127, u = i & 3;
        cp16(base + (uint32_t)(SQ_B + r * ROWB + u * 16),
             Bh + (size_t)(brow0 + r) * SEQ + k0 + u * 8);
    }
    CP_COMMIT();
}

__global__ __launch_bounds__(256)
void seq_hmma1(const __half* __restrict__ BkxT, const __half* __restrict__ BvT,
               float* __restrict__ part_kp, float* __restrict__ part_T)
{
    extern __shared__ char smem[];
    const uint32_t sb = smem_u32(smem);
    const int tid = threadIdx.x, wid = tid >> 5, lane = tid & 31;
    const int n0 = blockIdx.x * 128, b = blockIdx.y;
    const int which = blockIdx.z >> 2, seg = blockIdx.z & 3;
    const __half* Bh = which ? BvT : BkxT;
    float* part = which ? part_T : part_kp;
    const int brow0 = b * DMODEL + n0;
    const int kbase = seg * 1024;

    float acc[4][2][4];
#pragma unroll
    for (int i = 0; i < 4; ++i)
#pragma unroll
        for (int j = 0; j < 2; ++j)
#pragma unroll
            for (int c = 0; c < 4; ++c) acc[i][j][c] = 0.f;

    uint32_t aoff[4];
#pragma unroll
    for (int atom = 0; atom < 4; ++atom)
        aoff[atom] = (uint32_t)((atom * 16 + (lane & 15)) * ROWB + ((lane >> 4) & 1) * 16);
    const uint32_t boff = (uint32_t)((wid * 16 + (lane & 7) + ((lane >> 4) << 3)) * ROWB
                                     + ((lane >> 3) & 1) * 16);

    const __half* Ah = g_wxhi;
    seq_load_stage1(sb, 0, kbase + 0,  brow0, tid, Ah, Bh);
    seq_load_stage1(sb, 1, kbase + 32, brow0, tid, Ah, Bh);

    for (int kc = 0; kc < 32; ++kc) {
        if (kc >= 30) { CP_WAIT(0); } else { CP_WAIT(1); }
        __syncthreads();
        if (kc + 2 < 32)
            seq_load_stage1(sb, (kc + 2) % 3, kbase + (kc + 2) * 32, brow0, tid, Ah, Bh);
        const uint32_t stgb = sb + (uint32_t)(kc % 3) * SQ_STG;
#pragma unroll
        for (int ks = 0; ks < 2; ++ks) {
            const uint32_t kb = (uint32_t)(ks * 32);
            uint32_t ahi[4][4], bhi[4];
#pragma unroll
            for (int atom = 0; atom < 4; ++atom)
                ldsm4(ahi[atom], stgb + aoff[atom] + kb);
            ldsm4(bhi, stgb + SQ_B + boff + kb);
#pragma unroll
            for (int im = 0; im < 4; ++im)
#pragma unroll
                for (int in = 0; in < 2; ++in)
                    mma16816(acc[im][in], ahi[im], &bhi[in * 2]);
        }
    }

    const size_t obase = (size_t)seg * (BATCH * DKC * DMODEL);
#pragma unroll
    for (int im = 0; im < 4; ++im)
#pragma unroll
        for (int in = 0; in < 2; ++in) {
            const int n = n0 + wid * 16 + in * 8 + (lane & 3) * 2;
#pragma unroll
            for (int half = 0; half < 2; ++half) {
                const int e = im * 16 + (lane >> 2) + half * 8;
                *(float2*)(part + obase + ((size_t)(b * DKC + e) << 10) + n) =
                    make_float2(acc[im][in][half * 2], acc[im][in][half * 2 + 1]);
            }
        }
}

__global__ void finish_kpT(const float* __restrict__ wxb) {
    const int N = BATCH * DKC * DMODEL;
    int idx = blockIdx.x * blockDim.x + threadIdx.x;
    if (idx < N) {
        float v = 0.f;
#pragma unroll
        for (int s = 0; s < NSEG; ++s) v += g_kp_part[s * N + idx];
        g_kp[idx] = v + wxb[(idx >> 10) & 63];
    } else {
        int j = idx - N;
        float v = 0.f;
#pragma unroll
        for (int s = 0; s < NSEG; ++s) v += g_T_part[s * N + j];
        g_T[j] = v;
    }
}

// ================= qs: split-K SIMT GEMM (rows s<64 only) =================
__global__ __launch_bounds__(256)
void qs_gemm(const float* __restrict__ q, const float* __restrict__ wq)
{
    __shared__ float As[16][68];
    __shared__ float Bs[16][68];
    const int n0 = blockIdx.x * 64, b = blockIdx.y, seg = blockIdx.z;
    const int tid = threadIdx.x;
    const int ti = tid & 15, te = tid >> 4;
    const int lr = tid >> 2, lc = (tid & 3) * 4;

    float acc[4][4];
#pragma unroll
    for (int i = 0; i < 4; ++i)
#pragma unroll
        for (int j = 0; j < 4; ++j) acc[i][j] = 0.f;

    for (int kt = 0; kt < 16; ++kt) {
        const int k0 = seg * 256 + kt * 16;
        float4 pa = *(const float4*)(q  + ((size_t)b * SEQ + lr) * DMODEL + k0 + lc);
        float4 pb = *(const float4*)(wq + (size_t)(n0 + lr) * DMODEL + k0 + lc);
        As[lc + 0][lr] = pa.x; As[lc + 1][lr] = pa.y; As[lc + 2][lr] = pa.z; As[lc + 3][lr] = pa.w;
        Bs[lc + 0][lr] = pb.x; Bs[lc + 1][lr] = pb.y; Bs[lc + 2][lr] = pb.z; Bs[lc + 3][lr] = pb.w;
        __syncthreads();
#pragma unroll
        for (int kk = 0; kk < 16; ++kk) {
            float a[4], bb[4];
            *(float4*)a  = *(const float4*)&As[kk][te * 4];
            *(float4*)bb = *(const float4*)&Bs[kk][ti * 4];
#pragma unroll
            for (int i = 0; i < 4; ++i)
#pragma unroll
                for (int j = 0; j < 4; ++j)
                    acc[i][j] = fmaf(a[i], bb[j], acc[i][j]);
        }
        __syncthreads();
    }
    const size_t obase = (size_t)seg * (BATCH * DKC * DMODEL);
#pragma unroll
    for (int i = 0; i < 4; ++i)
#pragma unroll
        for (int j = 0; j < 4; ++j)
            g_qs_part[obase + ((size_t)(b * DKC + te * 4 + i) << 10) + n0 + ti * 4 + j] = acc[i][j];
}

__global__ void finish_qs() {
    int idx = blockIdx.x * blockDim.x + threadIdx.x;
    int m = idx >> 9, pr = idx & 511;
    float v0 = 0.f, v1 = 0.f;
#pragma unroll
    for (int s = 0; s < NSEG; ++s) {
        const float* p = g_qs_part + (size_t)s * (BATCH * DKC * DMODEL) + ((size_t)m << 10) + pr * 2;
        v0 += p[0]; v1 += p[1];
    }
    int sq = m & 63;
    int p = sq * HALF + pr;
    float cs = g_cos[p], sn = g_sin[p];
    g_qs[((size_t)m << 10) + pr * 2]     = v0 * cs - v1 * sn;
    g_qs[((size_t)m << 10) + pr * 2 + 1] = v1 * cs + v0 * sn;
}

// ================= vp[b,f,e] = sum_c wv[f,c]*T[b,e,c] + wxb[e] =================
__global__ __launch_bounds__(256)
void vp_kernel(const float* __restrict__ wv, const float* __restrict__ wxb)
{
    __shared__ float Wvs[64][68];
    __shared__ float Ts[64][68];
    const int f0 = blockIdx.x * 64;
    const int b  = blockIdx.y;
    const int tid = threadIdx.x;
    const int tf = tid & 15, te = tid >> 4;
    float acc[4][4];
#pragma unroll
    for (int a = 0; a < 4; ++a)
#pragma unroll
        for (int j = 0; j < 4; ++j) acc[a][j] = 0.f;

    for (int ch = 0; ch < 16; ++ch) {
        int cb = ch * 64;
#pragma unroll
        for (int r = 0; r < 16; ++r) {
            int l = r * 256 + tid;
            int row = l >> 6, col = l & 63;
            Wvs[row][col] = wv[(f0 + row) * DMODEL + cb + col];
            Ts[row][col]  = g_T[(b * DKC + row) * DMODEL + cb + col];
        }
        __syncthreads();
        for (int c = 0; c < 64; ++c) {
            float wf0 = Wvs[tf * 4 + 0][c], wf1 = Wvs[tf * 4 + 1][c];
            float wf2 = Wvs[tf * 4 + 2][c], wf3 = Wvs[tf * 4 + 3][c];
            float t0 = Ts[te * 4 + 0][c], t1 = Ts[te * 4 + 1][c];
            float t2 = Ts[te * 4 + 2][c], t3 = Ts[te * 4 + 3][c];
            acc[0][0] += wf0 * t0; acc[0][1] += wf0 * t1; acc[0][2] += wf0 * t2; acc[0][3] += wf0 * t3;
            acc[1][0] += wf1 * t0; acc[1][1] += wf1 * t1; acc[1][2] += wf1 * t2; acc[1][3] += wf1 * t3;
            acc[2][0] += wf2 * t0; acc[2][1] += wf2 * t1; acc[2][2] += wf2 * t2; acc[2][3] += wf2 * t3;
            acc[3][0] += wf3 * t0; acc[3][1] += wf3 * t1; acc[3][2] += wf3 * t2; acc[3][3] += wf3 * t3;
        }
        __syncthreads();
    }
#pragma unroll
    for (int a = 0; a < 4; ++a)
#pragma unroll
        for (int j = 0; j < 4; ++j) {
            int f = f0 + tf * 4 + a, e = te * 4 + j;
            g_vp[(b * DMODEL + f) * DKC + e] = acc[a][j] + wxb[e];
        }
}

// ================= tiny attention (s < 64 rows) =================
__global__ __launch_bounds__(64)
void attn_small()
{
    __shared__ float kps[64][64];
    __shared__ float vps[64][64];
    const int h = blockIdx.x, b = blockIdx.y, s = threadIdx.x;
#pragma unroll 4
    for (int e = 0; e < 64; ++e)
        kps[s][e] = g_kp[((size_t)(b * DKC + e) << 10) + h * DKC + s];
    for (int l = s; l < 4096; l += 64) {
        int d = l >> 6, e = l & 63;
        vps[d][e] = g_vp[(b * DMODEL + h * DKC + d) * DKC + e];
    }
    __syncthreads();

    float qv[64];
    const float* qp = g_qs + (b * DKC + s) * DMODEL + h * DKC;
#pragma unroll
    for (int d = 0; d < 64; d += 4) {
        float4 t = *(const float4*)(qp + d);
        qv[d] = t.x; qv[d + 1] = t.y; qv[d + 2] = t.z; qv[d + 3] = t.w;
    }
    const float lg0 = logf(1.0f / 32.0f);
    const float lg1 = logf(1.0f / 512.0f);
    const float gamma = 1.0f - expf(lg0 + (lg1 - lg0) * ((float)h / 15.0f));

    float sc[64];
#pragma unroll
    for (int e = 0; e < 64; ++e) {
        float a = 0.f;
#pragma unroll
        for (int d = 0; d < 64; ++d) a = fmaf(qv[d], kps[d][e], a);
        float dt = (e >= s) ? powf(gamma, (float)(e - s)) : 0.0f;
        sc[e] = a * dt;
    }
    float mx = -1e30f;
#pragma unroll
    for (int e = 0; e < 64; ++e) mx = fmaxf(mx, sc[e]);
    float sum = 0.f;
#pragma unroll
    for (int e = 0; e < 64; ++e) { sc[e] = expf(sc[e] - mx); sum += sc[e]; }
    float inv = 1.0f / sum;
#pragma unroll
    for (int f = 0; f < 64; ++f) {
        float a = 0.f;
#pragma unroll
        for (int e = 0; e < 64; ++e) a = fmaf(sc[e], vps[f][e], a);
        g_ysmall[(b * DKC + s) * DMODEL + h * DKC + f] = a * inv;
    }
}

// ================= group norm =================
__device__ __forceinline__ void gn4(float y[4], int d0,
                                    const float* gw, const float* gb, float out[4]) {
    float mu = (y[0] + y[1] + y[2] + y[3]) * 0.25f;
    float var = 0.f;
#pragma unroll
    for (int j = 0; j < 4; ++j) { float dd = y[j] - mu; var += dd * dd; }
    var *= 0.25f;
    float inv = rsqrtf(var + 1e-5f);
#pragma unroll
    for (int j = 0; j < 4; ++j) {
        int d = d0 + j;
        out[j] = (y[j] - mu) * inv * gw[d & 63] + gb[d & 63];
    }
}

__global__ void zbar_kernel(const float* __restrict__ gw, const float* __restrict__ gb) {
    int b = blockIdx.x, t = threadIdx.x;
    int d0 = t * 4;
    float y[4];
#pragma unroll
    for (int j = 0; j < 4; ++j) {
        const float* vp = g_vp + (b * DMODEL + d0 + j) * DKC;
        float s = 0.f;
#pragma unroll
        for (int e = 0; e < 64; ++e) s += vp[e];
        y[j] = s * (1.0f / 64.0f);
    }
    float o[4];
    gn4(y, d0, gw, gb, o);
#pragma unroll
    for (int j = 0; j < 4; ++j) g_zbar[b * DMODEL + d0 + j] = o[j];
}

__global__ void gn_small(const float* __restrict__ gw, const float* __restrict__ gb) {
    int row = blockIdx.x;
    int d0 = threadIdx.x * 4;
    float4 y4 = *(const float4*)(g_ysmall + row * DMODEL + d0);
    float y[4] = { y4.x, y4.y, y4.z, y4.w };
    float o[4];
    gn4(y, d0, gw, gb, o);
    *(float4*)(g_z + row * DMODEL + d0) = make_float4(o[0], o[1], o[2], o[3]);
}

// ================= launch =================
extern "C" void kernel_launch(void* const* d_in, const int* in_sizes, int n_in,
                              void* d_out, int out_size)
{
    const float* q   = (const float*)d_in[0];
    const float* k   = (const float*)d_in[1];
    const float* v   = (const float*)d_in[2];
    const float* wq  = (const float*)d_in[3];
    const float* wk  = (const float*)d_in[4];
    const float* wv  = (const float*)d_in[5];
    const float* wo  = (const float*)d_in[6];
    const float* wg  = (const float*)d_in[7];
    const float* wxw = (const float*)d_in[8];
    const float* wxb = (const float*)d_in[9];
    const float* gnw = (const float*)d_in[10];
    const float* gnb = (const float*)d_in[11];
    float* out = (float*)d_out;

    float *p_kpp, *p_tp;
    cudaGetSymbolAddress((void**)&p_kpp, g_kp_part);
    cudaGetSymbolAddress((void**)&p_tp,  g_T_part);

    __half *p_qhi, *p_khi, *p_ahi;
    __half *p_wkhi, *p_wghi, *p_wohi, *p_wxhi;
    __half *p_kxThi, *p_vThi;
    cudaGetSymbolAddress((void**)&p_qhi,  g_qhi);
    cudaGetSymbolAddress((void**)&p_khi,  g_khi);
    cudaGetSymbolAddress((void**)&p_ahi,  g_ahi);
    cudaGetSymbolAddress((void**)&p_wkhi, g_wkhi);
    cudaGetSymbolAddress((void**)&p_wghi, g_wghi);
    cudaGetSymbolAddress((void**)&p_wohi, g_wohi);
    cudaGetSymbolAddress((void**)&p_wxhi, g_wxhi);
    cudaGetSymbolAddress((void**)&p_kxThi, g_kxThi);
    cudaGetSymbolAddress((void**)&p_vThi,  g_vThi);

    cudaFuncSetAttribute((const void*)hmma_gemm<0>, cudaFuncAttributeMaxDynamicSharedMemorySize, SMEM_MAIN);
    cudaFuncSetAttribute((const void*)hmma_gemm<1>, cudaFuncAttributeMaxDynamicSharedMemorySize, SMEM_MAIN);
    cudaFuncSetAttribute((const void*)hmma_gemm<2>, cudaFuncAttributeMaxDynamicSharedMemorySize, SMEM_MAIN);
    cudaFuncSetAttribute((const void*)seq_hmma1, cudaFuncAttributeMaxDynamicSharedMemorySize, SMEM_SEQ);

    build_tables<<<(SEQ * HALF + 255) / 256, 256>>>();

    const int nact4 = MTOT * DMODEL / 4;
    const int nw4   = DMODEL * DMODEL / 4;
    const int nwx4  = DKC * SEQ / 4;
    conv_qk<<<dim3(nact4 / 256, 2), 256>>>(q, k, p_qhi, p_khi, nact4);
    conv_w <<<dim3(nw4 / 256, 3), 256>>>(wk, wg, wo, p_wkhi, p_wghi, p_wohi, nw4);
    split_hi<<<nwx4 / 256, 256>>>(wxw, p_wxhi, nwx4);

    vt_split<<<dim3(SEQ / 64, DMODEL / 64, BATCH), 256>>>(v, p_vThi);

    // keyxT = xpos(k @ wk^T)^T fp16, 1-pass HMMA
    hmma_gemm<1><<<dim3(8, 128), 512, SMEM_MAIN>>>(p_khi, p_wkhi, nullptr, p_kxThi);
    // qs = xpos(q @ wq^T) rows s<64 (fp32)
    qs_gemm<<<dim3(16, BATCH, NSEG), 256>>>(q, wq);
    finish_qs<<<(BATCH * DKC * HALF) / 256, 256>>>();

    // kp & T seq contractions, merged 1-term launch (256 CTAs = full wave)
    seq_hmma1<<<dim3(8, BATCH, 2 * NSEG), 256, SMEM_SEQ>>>(p_kxThi, p_vThi, p_kpp, p_tp);
    finish_kpT<<<(2 * BATCH * DKC * DMODEL) / 256, 256>>>(wxb);

    vp_kernel<<<dim3(16, BATCH), 256>>>(wv, wxb);
    attn_small<<<dim3(HEADS, BATCH), 64>>>();
    zbar_kernel<<<BATCH, 256>>>(gnw, gnb);
    gn_small<<<BATCH * DKC, 256>>>(gnw, gnb);

    // act = silu((q @ wg^T) * z) -> fp16, 1-pass HMMA
    hmma_gemm<2><<<dim3(8, 128), 512, SMEM_MAIN>>>(p_qhi, p_wghi, nullptr, p_ahi);
    // out = act @ wo^T, 1-pass HMMA
    hmma_gemm<0><<<dim3(8, 128), 512, SMEM_MAIN>>>(p_ahi, p_wohi, out, nullptr);
}